// round 15
// baseline (speedup 1.0000x reference)
#include <cuda_runtime.h>
#include <cuda_bf16.h>
#include <math.h>
#include <stdint.h>

#define DIM     512
#define HEADS   8
#define DFF     1365
#define DFFP    1408            // DFF padded (K multiple of 32)
#define CROWS   1024            // compressed rows: (g,b,n)
#define NBIG    3756            // 512 + 2730 + 512 + 2 align pad
#define QRES_OFF 3242           // 512 + 2730
#define RMS_EPS 1.1920929e-07f

// ---------------- scratch (device globals) ----------------
static __device__ float g_B   [CROWS * NBIG];     // [Q | (ff unused) | Qres]
static __device__ float g_T   [CROWS * DIM];
static __device__ float g_KV  [CROWS * 1024];
static __device__ float g_kvm [512 * 1024 + 6 * 1024 * 1024]; // tok + (att,ret)x3
static __device__ float g_bias[NBIG];
static __device__ float g_bret[1024];
static __device__ float g_pacc[128 * 64 * 256];
static __device__ float g_pml [128 * 2 * 256];
static __device__ float g_part[1 << 21];          // split-K partials

static __device__ __nv_bfloat16 g_XNh[CROWS * DIM],  g_XNl[CROWS * DIM];
static __device__ __nv_bfloat16 g_XAh[CROWS * DIM],  g_XAl[CROWS * DIM];
static __device__ __nv_bfloat16 g_ACTh[CROWS * DFFP], g_ACTl[CROWS * DFFP]; // pad cols stay 0
static __device__ __nv_bfloat16 g_XRh[CROWS * DIM],  g_XRl[CROWS * DIM];
static __device__ __nv_bfloat16 g_Th [CROWS * DIM],  g_Tl [CROWS * DIM];

static __device__ __nv_bfloat16 g_Wbigh[NBIG * 512], g_Wbigl[NBIG * 512];
static __device__ __nv_bfloat16 g_Wkvh[1024 * 512],  g_Wkvl[1024 * 512];
static __device__ __nv_bfloat16 g_Rkvh[1024 * 512],  g_Rkvl[1024 * 512];
static __device__ __nv_bfloat16 g_WoTh[512 * 512],   g_WoTl[512 * 512];
static __device__ __nv_bfloat16 g_WvpTh[DFFP * 512], g_WvpTl[DFFP * 512];
static __device__ __nv_bfloat16 g_Rwoh[512 * 512],   g_Rwol[512 * 512];
static __device__ __nv_bfloat16 g_Cath[1024 * 512],  g_Catl[1024 * 512];
static __device__ __nv_bfloat16 g_Creth[1024 * DFFP], g_Cretl[1024 * DFFP];

// ---------------- helpers ----------------
__device__ __forceinline__ void split_bf16(float v, __nv_bfloat16& h, __nv_bfloat16& l) {
    h = __float2bfloat16(v);
    l = __float2bfloat16(v - __bfloat162float(h));
}
__device__ __forceinline__ uint32_t smem_u32(const void* p) {
    uint32_t a;
    asm("{ .reg .u64 t; cvta.to.shared.u64 t, %1; cvt.u32.u64 %0, t; }" : "=r"(a) : "l"(p));
    return a;
}
__device__ __forceinline__ void cp16(uint32_t dst, const void* src, uint32_t sz) {
    asm volatile("cp.async.cg.shared.global [%0], [%1], 16, %2;"
                 :: "r"(dst), "l"(src), "r"(sz));
}
__device__ __forceinline__ void ldsm4(uint32_t& r0, uint32_t& r1, uint32_t& r2,
                                      uint32_t& r3, uint32_t addr) {
    asm volatile("ldmatrix.sync.aligned.m8n8.x4.shared.b16 {%0,%1,%2,%3}, [%4];"
                 : "=r"(r0), "=r"(r1), "=r"(r2), "=r"(r3) : "r"(addr));
}
__device__ __forceinline__ void mma16816(float* c, const uint32_t* a, const uint32_t* b) {
    asm volatile(
        "mma.sync.aligned.m16n8k16.row.col.f32.bf16.bf16.f32 "
        "{%0,%1,%2,%3}, {%4,%5,%6,%7}, {%8,%9}, {%0,%1,%2,%3};"
        : "+f"(c[0]), "+f"(c[1]), "+f"(c[2]), "+f"(c[3])
        : "r"(a[0]), "r"(a[1]), "r"(a[2]), "r"(a[3]), "r"(b[0]), "r"(b[1]));
}
__device__ __forceinline__ float gelu_pair(float sim, float gate) {
    return sim * (0.5f * gate * (1.0f + erff(gate * 0.70710678118654752440f)));
}

// ---------------- GEMM core (split-bf16, 3-stage cp.async; R11 config) ----------
// 128x64 block tile, 256 threads = 8 warps of 32x32 (4M x 2N layout).
#define GSTAGE   30720
#define GSMEM    (3 * GSTAGE)
#define GTHREADS 256

__device__ __forceinline__ void g_loads(
    uint32_t sb, int tid, int buf, int ck,
    const __nv_bfloat16* Ah, const __nv_bfloat16* Al, int lda,
    const __nv_bfloat16* Bh, const __nv_bfloat16* Bl,
    int K, int N, int bm0, int bn0)
{
    const uint32_t bufbase = sb + (uint32_t)buf * GSTAGE;
#pragma unroll
    for (int i = 0; i < 6; i++) {
        int c = tid + i * GTHREADS;
        int R = c >> 2;
        int q = c & 3;
        uint32_t dst = bufbase + (uint32_t)R * 80u + (uint32_t)q * 16u;
        const __nv_bfloat16* src;
        uint32_t sz = 16;
        if (R < 256) {
            src = (R < 128 ? Ah : Al) + (size_t)(bm0 + (R & 127)) * lda;
        } else {
            int rg = bn0 + (R & 63);
            if (rg >= N) { rg = 0; sz = 0; }
            src = (R < 320 ? Bh : Bl) + (size_t)rg * K;
        }
        cp16(dst, src + ck * 32 + q * 8, sz);
    }
    asm volatile("cp.async.commit_group;");
}

__device__ __forceinline__ void gemm_core(
    const __nv_bfloat16* Ah, const __nv_bfloat16* Al, int lda,
    const __nv_bfloat16* Bh, const __nv_bfloat16* Bl,
    const float* bias, float* Yf, __nv_bfloat16* Yh, __nv_bfloat16* Yl,
    int M, int N, int K, int splitk, float* Pf, int mode,
    int bn0, int bm0, int z)
{
    extern __shared__ __align__(16) char smem[];
    const uint32_t sb = smem_u32(smem);
    const int tid  = threadIdx.x;
    const int wid  = tid >> 5;
    const int lane = tid & 31;
    const int m0w  = (wid & 3) * 32;
    const int n0w  = (wid >> 2) * 32;

    float C[2][4][4];
#pragma unroll
    for (int mt = 0; mt < 2; mt++)
#pragma unroll
        for (int nt = 0; nt < 4; nt++)
#pragma unroll
            for (int v = 0; v < 4; v++) C[mt][nt][v] = 0.f;

    uint32_t aoffH[2], aoffL[2], boffH[2], boffL[2];
#pragma unroll
    for (int mt = 0; mt < 2; mt++) {
        uint32_t row = (uint32_t)(m0w + mt * 16 + (lane & 15));
        uint32_t kb  = (uint32_t)((lane >> 4) * 16);
        aoffH[mt] = sb + row * 80u + kb;
        aoffL[mt] = aoffH[mt] + 10240u;
    }
#pragma unroll
    for (int bt = 0; bt < 2; bt++) {
        uint32_t row = (uint32_t)(n0w + bt * 16 + (lane & 7) + ((lane >> 4) << 3));
        uint32_t kb  = (uint32_t)(((lane >> 3) & 1) * 16);
        boffH[bt] = sb + 20480u + row * 80u + kb;
        boffL[bt] = boffH[bt] + 5120u;
    }

    const int kspan = K / splitk;
    const int nk    = kspan >> 5;
    const int kb32  = z * nk;
    g_loads(sb, tid, 0, kb32 + 0, Ah, Al, lda, Bh, Bl, K, N, bm0, bn0);
    g_loads(sb, tid, 1, kb32 + 1, Ah, Al, lda, Bh, Bl, K, N, bm0, bn0);

    int buf = 0;
    for (int t = 0; t < nk; t++) {
        if (t < nk - 1) asm volatile("cp.async.wait_group 1;" ::: "memory");
        else            asm volatile("cp.async.wait_group 0;" ::: "memory");
        __syncthreads();

        if (t + 2 < nk) {
            int lb = buf + 2; if (lb >= 3) lb -= 3;
            g_loads(sb, tid, lb, kb32 + t + 2, Ah, Al, lda, Bh, Bl, K, N, bm0, bn0);
        }

        const uint32_t bofs = (uint32_t)buf * GSTAGE;
#pragma unroll
        for (int ks = 0; ks < 2; ks++) {
            const uint32_t ko = bofs + (uint32_t)ks * 32u;
            uint32_t ah[2][4], al[2][4], bh[4][2], bl[4][2];
#pragma unroll
            for (int mt = 0; mt < 2; mt++) {
                ldsm4(ah[mt][0], ah[mt][1], ah[mt][2], ah[mt][3], aoffH[mt] + ko);
                ldsm4(al[mt][0], al[mt][1], al[mt][2], al[mt][3], aoffL[mt] + ko);
            }
            ldsm4(bh[0][0], bh[0][1], bh[1][0], bh[1][1], boffH[0] + ko);
            ldsm4(bh[2][0], bh[2][1], bh[3][0], bh[3][1], boffH[1] + ko);
            ldsm4(bl[0][0], bl[0][1], bl[1][0], bl[1][1], boffL[0] + ko);
            ldsm4(bl[2][0], bl[2][1], bl[3][0], bl[3][1], boffL[1] + ko);
#pragma unroll
            for (int mt = 0; mt < 2; mt++)
#pragma unroll
                for (int nt = 0; nt < 4; nt++) {
                    mma16816(C[mt][nt], ah[mt], bh[nt]);
                    mma16816(C[mt][nt], ah[mt], bl[nt]);
                    mma16816(C[mt][nt], al[mt], bh[nt]);
                }
        }
        buf = (buf == 2) ? 0 : buf + 1;
    }

    if (splitk > 1) {
        float* P = Pf + (size_t)z * M * N;
#pragma unroll
        for (int mt = 0; mt < 2; mt++) {
            const int row = bm0 + m0w + mt * 16 + (lane >> 2);
#pragma unroll
            for (int nt = 0; nt < 4; nt++) {
                const int col = bn0 + n0w + nt * 8 + (lane & 3) * 2;
                if (col < N) {
                    *reinterpret_cast<float2*>(P + (size_t)row * N + col)
                        = make_float2(C[mt][nt][0], C[mt][nt][1]);
                    *reinterpret_cast<float2*>(P + (size_t)(row + 8) * N + col)
                        = make_float2(C[mt][nt][2], C[mt][nt][3]);
                }
            }
        }
        return;
    }

#pragma unroll
    for (int mt = 0; mt < 2; mt++) {
        const int row = bm0 + m0w + mt * 16 + (lane >> 2);
#pragma unroll
        for (int nt = 0; nt < 4; nt++) {
            const int col = bn0 + n0w + nt * 8 + (lane & 3) * 2;
            if (col < N) {
                float b0 = bias ? bias[col]     : 0.f;
                float b1 = bias ? bias[col + 1] : 0.f;
                float v00 = C[mt][nt][0] + b0, v01 = C[mt][nt][1] + b1;
                float v10 = C[mt][nt][2] + b0, v11 = C[mt][nt][3] + b1;
                if (mode == 1) {
                    if (col >= 512 && col < QRES_OFF) {
                        int e = (col - 512) >> 1;
                        float a0 = gelu_pair(v00, v01);
                        float a1 = gelu_pair(v10, v11);
                        __nv_bfloat16 h, l;
                        split_bf16(a0, h, l);
                        Yh[(size_t)row * DFFP + e] = h;
                        Yl[(size_t)row * DFFP + e] = l;
                        split_bf16(a1, h, l);
                        Yh[(size_t)(row + 8) * DFFP + e] = h;
                        Yl[(size_t)(row + 8) * DFFP + e] = l;
                    } else {
                        *reinterpret_cast<float2*>(Yf + (size_t)row * N + col)
                            = make_float2(v00, v01);
                        *reinterpret_cast<float2*>(Yf + (size_t)(row + 8) * N + col)
                            = make_float2(v10, v11);
                    }
                    continue;
                }
                const size_t o0 = (size_t)row * N + col;
                const size_t o1 = (size_t)(row + 8) * N + col;
                if (Yf) {
                    *reinterpret_cast<float2*>(Yf + o0) = make_float2(v00, v01);
                    *reinterpret_cast<float2*>(Yf + o1) = make_float2(v10, v11);
                }
                if (Yh) {
                    __nv_bfloat16 h0, l0, h1, l1;
                    split_bf16(v00, h0, l0); split_bf16(v01, h1, l1);
                    *reinterpret_cast<__nv_bfloat162*>(Yh + o0) = __nv_bfloat162(h0, h1);
                    *reinterpret_cast<__nv_bfloat162*>(Yl + o0) = __nv_bfloat162(l0, l1);
                    split_bf16(v10, h0, l0); split_bf16(v11, h1, l1);
                    *reinterpret_cast<__nv_bfloat162*>(Yh + o1) = __nv_bfloat162(h0, h1);
                    *reinterpret_cast<__nv_bfloat162*>(Yl + o1) = __nv_bfloat162(l0, l1);
                }
            }
        }
    }
}

// ---------------- single-task GEMM (supports split-K) ----------------
__global__ __launch_bounds__(GTHREADS) void gemm_mma(
    const __nv_bfloat16* __restrict__ Ah, const __nv_bfloat16* __restrict__ Al, int lda,
    const __nv_bfloat16* __restrict__ Bh, const __nv_bfloat16* __restrict__ Bl,
    const float* __restrict__ bias,
    float* __restrict__ Yf, __nv_bfloat16* __restrict__ Yh, __nv_bfloat16* __restrict__ Yl,
    int M, int N, int K, int splitk, float* __restrict__ Pf, int mode)
{
    gemm_core(Ah, Al, lda, Bh, Bl, bias, Yf, Yh, Yl, M, N, K, splitk, Pf, mode,
              blockIdx.x * 64, blockIdx.y * 128, blockIdx.z);
}

// ---------------- grouped GEMM (Bresenham-interleaved task assignment) ----------
struct GTask {
    const __nv_bfloat16 *Ah, *Al, *Bh, *Bl;
    const float* bias;
    float* Yf;
    __nv_bfloat16 *Yh, *Yl;
    int lda, M, N, K, mode, nx, nblocks;
};

__global__ __launch_bounds__(GTHREADS) void gemm_group(GTask t0, GTask t1, GTask t2)
{
    int bx  = blockIdx.x;
    int tot = t0.nblocks + t1.nblocks + t2.nblocks;

    GTask t;
    // level 1: t0 vs (t1,t2), proportionally interleaved
    long p0   = (long)bx * t0.nblocks;
    int  i0   = (int)(p0 / tot);
    bool is0  = (int)((p0 + t0.nblocks) / tot) > i0;
    if (is0) {
        t = t0; bx = i0;
    } else {
        int b12  = bx - i0;                 // index within t1+t2 stream
        int n12  = t1.nblocks + t2.nblocks;
        long p1  = (long)b12 * t1.nblocks;
        int  i1  = (int)(p1 / n12);
        bool is1 = (int)((p1 + t1.nblocks) / n12) > i1;
        if (is1) { t = t1; bx = i1; }
        else     { t = t2; bx = b12 - i1; }
    }
    int bn0 = (bx % t.nx) * 64;
    int bm0 = (bx / t.nx) * 128;
    gemm_core(t.Ah, t.Al, t.lda, t.Bh, t.Bl, t.bias, t.Yf, t.Yh, t.Yl,
              t.M, t.N, t.K, 1, nullptr, t.mode, bn0, bm0, 0);
}

// ---------------- split-K combine (optional expanded fanout output) -------------
__global__ __launch_bounds__(256) void splitk_combine(
    const float* __restrict__ P, int parts, int MN, int N,
    const float* __restrict__ bias,
    float* __restrict__ Yf,
    __nv_bfloat16* __restrict__ Yh, __nv_bfloat16* __restrict__ Yl,
    float* __restrict__ Yexp)
{
    int idx = (blockIdx.x * 256 + threadIdx.x) * 2;
    if (idx >= MN) return;
    float2 a = *reinterpret_cast<const float2*>(P + idx);
    for (int p = 1; p < parts; p++) {
        float2 b = *reinterpret_cast<const float2*>(P + (size_t)p * MN + idx);
        a.x += b.x; a.y += b.y;
    }
    if (bias) {
        int col = idx % N;
        a.x += bias[col];
        a.y += bias[col + 1];
    }
    if (Yexp) {
        int row = idx / N;
        int col = idx - row * N;
        int g   = row >> 9;
        int rem = row & 511;
#pragma unroll
        for (int j = 0; j < 3; j++) {
            int r2 = ((3 * g + j) << 9) + rem;
            *reinterpret_cast<float2*>(Yexp + (size_t)r2 * N + col) = a;
        }
        return;
    }
    if (Yf) *reinterpret_cast<float2*>(Yf + idx) = a;
    if (Yh) {
        __nv_bfloat16 h0, l0, h1, l1;
        split_bf16(a.x, h0, l0); split_bf16(a.y, h1, l1);
        *reinterpret_cast<__nv_bfloat162*>(Yh + idx) = __nv_bfloat162(h0, h1);
        *reinterpret_cast<__nv_bfloat162*>(Yl + idx) = __nv_bfloat162(l0, l1);
    }
}

// ---------------- fused split-K combine + RMSNorm (block per 512-col row) -------
// Sums partials (rwo output, no bias), writes T / Th / Tl, then computes the
// row rmsnorm and writes XNh / XNl for the next exchange.
__global__ __launch_bounds__(256) void combine_rms(
    const float* __restrict__ P, int parts,
    float* __restrict__ T,
    __nv_bfloat16* __restrict__ Th, __nv_bfloat16* __restrict__ Tl,
    __nv_bfloat16* __restrict__ XNh, __nv_bfloat16* __restrict__ XNl)
{
    const int row = blockIdx.x;
    const int tid = threadIdx.x;
    const int idx = row * DIM + tid * 2;
    const int MN  = CROWS * DIM;

    __shared__ float red[8];

    float2 a = *reinterpret_cast<const float2*>(P + idx);
    for (int p = 1; p < parts; p++) {
        float2 b = *reinterpret_cast<const float2*>(P + (size_t)p * MN + idx);
        a.x += b.x; a.y += b.y;
    }

    *reinterpret_cast<float2*>(T + idx) = a;
    __nv_bfloat16 h0, l0, h1, l1;
    split_bf16(a.x, h0, l0); split_bf16(a.y, h1, l1);
    *reinterpret_cast<__nv_bfloat162*>(Th + idx) = __nv_bfloat162(h0, h1);
    *reinterpret_cast<__nv_bfloat162*>(Tl + idx) = __nv_bfloat162(l0, l1);

    // row sum of squares
    float ss = a.x * a.x + a.y * a.y;
#pragma unroll
    for (int o = 16; o > 0; o >>= 1) ss += __shfl_xor_sync(0xffffffffu, ss, o);
    if ((tid & 31) == 0) red[tid >> 5] = ss;
    __syncthreads();
    if (tid < 8) {
        float v = red[tid];
#pragma unroll
        for (int o = 4; o > 0; o >>= 1) v += __shfl_xor_sync(0xffu, v, o);
        if (tid == 0) red[0] = v;
    }
    __syncthreads();
    float rs = rsqrtf(red[0] * (1.0f / 512.0f) + RMS_EPS);

    split_bf16(a.x * rs, h0, l0); split_bf16(a.y * rs, h1, l1);
    *reinterpret_cast<__nv_bfloat162*>(XNh + idx) = __nv_bfloat162(h0, h1);
    *reinterpret_cast<__nv_bfloat162*>(XNl + idx) = __nv_bfloat162(l0, l1);
}

// ---------------- packed f32x2 helpers ----------------
__device__ __forceinline__ void ffma2(unsigned long long& d, unsigned long long a,
                                      unsigned long long b) {
    asm("fma.rn.f32x2 %0, %1, %2, %0;" : "+l"(d) : "l"(a), "l"(b));
}
__device__ __forceinline__ unsigned long long fma2_3(unsigned long long a,
                                                     unsigned long long b,
                                                     unsigned long long c) {
    unsigned long long d;
    asm("fma.rn.f32x2 %0, %1, %2, %3;" : "=l"(d) : "l"(a), "l"(b), "l"(c));
    return d;
}
__device__ __forceinline__ unsigned long long mul2(unsigned long long a,
                                                   unsigned long long b) {
    unsigned long long d;
    asm("mul.rn.f32x2 %0, %1, %2;" : "=l"(d) : "l"(a), "l"(b));
    return d;
}
__device__ __forceinline__ unsigned long long dup2(float x) {
    unsigned long long r;
    asm("mov.b64 %0, {%1, %1};" : "=l"(r) : "f"(x));
    return r;
}
__device__ __forceinline__ unsigned long long pk2(float x, float y) {
    unsigned long long r;
    asm("mov.b64 %0, {%1, %2};" : "=l"(r) : "f"(x), "f"(y));
    return r;
}
__device__ __forceinline__ float2 unpack2(unsigned long long v) {
    float2 f;
    asm("mov.b64 {%0, %1}, %2;" : "=f"(f.x), "=f"(f.y) : "l"(v));
    return f;
}

// ---------------- RMSNorm (used only for exchange 0 on init tokens) -------------
__global__ __launch_bounds__(256) void rmsnorm_now(
    const float* __restrict__ X,
    __nv_bfloat16* __restrict__ Yh, __nv_bfloat16* __restrict__ Yl, int rows)
{
    int row  = blockIdx.x * 8 + (threadIdx.x >> 5);
    int lane = threadIdx.x & 31;
    if (row >= rows) return;
    const float* xp = X + (size_t)row * DIM;
    float x[16];
    float ss = 0.f;
#pragma unroll
    for (int t = 0; t < 16; t++) { x[t] = xp[lane + t * 32]; ss += x[t] * x[t]; }
#pragma unroll
    for (int o = 16; o > 0; o >>= 1) ss += __shfl_xor_sync(0xffffffffu, ss, o);
    float rs = rsqrtf(ss * (1.0f / 512.0f) + RMS_EPS);
#pragma unroll
    for (int t = 0; t < 16; t++) {
        int c = lane + t * 32;
        __nv_bfloat16 h, l;
        split_bf16(x[t] * rs, h, l);
        Yh[(size_t)row * DIM + c] = h;
        Yl[(size_t)row * DIM + c] = l;
    }
}

// ---------------- Self attention, split over 4 key-chunks ----------------
__global__ __launch_bounds__(256) void self_attn_part(
    const float* __restrict__ Q, int ldq, const float* __restrict__ KV,
    float* __restrict__ pacc, float* __restrict__ pml, int nbatch)
{
    const int h     = blockIdx.x;
    const int batch = blockIdx.y;
    const int jc    = blockIdx.z;
    const int i     = threadIdx.x;
    const int j0    = jc * 64;

    __shared__ __align__(16) float Ks[64][64];
    __shared__ __align__(16) float Vs[64][64];

    unsigned long long qp[32];
    {
        const float4* qq = reinterpret_cast<const float4*>(
            Q + ((size_t)(batch * 256 + i)) * ldq + h * 64);
#pragma unroll
        for (int t = 0; t < 16; t++) {
            float4 v = qq[t];
            qp[2 * t]     = pk2(v.x, v.y);
            qp[2 * t + 1] = pk2(v.z, v.w);
        }
    }

#pragma unroll
    for (int s = 0; s < 4; s++) {
        int u  = threadIdx.x + s * 256;
        int jr = u >> 4;
        int c4 = u & 15;
        const float* kp = KV + ((size_t)(batch * 256 + j0 + jr)) * 1024 + h * 64 + c4 * 4;
        *reinterpret_cast<float4*>(&Ks[jr][c4 * 4]) = *reinterpret_cast<const float4*>(kp);
        *reinterpret_cast<float4*>(&Vs[jr][c4 * 4]) = *reinterpret_cast<const float4*>(kp + 512);
    }
    __syncthreads();

    float m = -1e30f, l = 0.f;
    unsigned long long acc[32];
#pragma unroll
    for (int t = 0; t < 32; t++) acc[t] = 0ull;

    for (int j = 0; j < 64; j++) {
        const ulonglong2* kr = reinterpret_cast<const ulonglong2*>(Ks[j]);
        unsigned long long s0 = 0ull, s1 = 0ull;
#pragma unroll
        for (int t = 0; t < 8; t++) {
            ulonglong2 k0 = kr[2 * t];
            ulonglong2 k1 = kr[2 * t + 1];
            ffma2(s0, qp[4 * t + 0], k0.x);
            ffma2(s1, qp[4 * t + 1], k0.y);
            ffma2(s0, qp[4 * t + 2], k1.x);
            ffma2(s1, qp[4 * t + 3], k1.y);
        }
        float2 sa = unpack2(s0), sb = unpack2(s1);
        float s = (sa.x + sa.y) + (sb.x + sb.y);

        float mn = fmaxf(m, s);
        float f  = __expf(m - mn);
        float p  = __expf(s - mn);
        l = l * f + p;
        unsigned long long fd = dup2(f), pd = dup2(p);
        const ulonglong2* vr = reinterpret_cast<const ulonglong2*>(Vs[j]);
#pragma unroll
        for (int t = 0; t < 16; t++) {
            ulonglong2 vv = vr[t];
            acc[2 * t]     = fma2_3(acc[2 * t],     fd, mul2(vv.x, pd));
            acc[2 * t + 1] = fma2_3(acc[2 * t + 1], fd, mul2(vv.y, pd));
        }
        m = mn;
    }

    const int bl = (jc * nbatch + batch) * HEADS + h;
    float* pa = pacc + ((size_t)bl * 64) * 256;
#pragma unroll
    for (int t = 0; t < 32; t++) {
        float2 a = unpack2(acc[t]);
        pa[(2 * t) * 256 + i]     = a.x;
        pa[(2 * t + 1) * 256 + i] = a.y;
    }
    pml[(bl * 2 + 0) * 256 + i] = m;
    pml[(bl * 2 + 1) * 256 + i] = l;
}

__global__ __launch_bounds__(256) void self_attn_combine(
    const float* __restrict__ pacc, const float* __restrict__ pml,
    __nv_bfloat16* __restrict__ Oh, __nv_bfloat16* __restrict__ Ol, int nbatch)
{
    int idx   = blockIdx.x * 256 + threadIdx.x;
    int i     = idx & 255;
    int h     = (idx >> 8) & 7;
    int batch = idx >> 11;

    float mc[4], lc[4];
    float M = -1e30f;
#pragma unroll
    for (int c = 0; c < 4; c++) {
        int bl = (c * nbatch + batch) * HEADS + h;
        mc[c] = pml[(bl * 2 + 0) * 256 + i];
        lc[c] = pml[(bl * 2 + 1) * 256 + i];
        M = fmaxf(M, mc[c]);
    }
    float w[4];
    float L = 0.f;
#pragma unroll
    for (int c = 0; c < 4; c++) { w[c] = __expf(mc[c] - M); L += lc[c] * w[c]; }
    float inv = 1.0f / L;

    size_t ob = ((size_t)(batch * 256 + i)) * 512 + h * 64;
#pragma unroll
    for (int t = 0; t < 64; t++) {
        float o = 0.f;
#pragma unroll
        for (int c = 0; c < 4; c++) {
            int bl = (c * nbatch + batch) * HEADS + h;
            o += w[c] * pacc[((size_t)bl * 64 + t) * 256 + i];
        }
        __nv_bfloat16 hh, ll;
        split_bf16(o * inv, hh, ll);
        Oh[ob + t] = hh;
        Ol[ob + t] = ll;
    }
}

// ---------------- Residual attention over unique messages ----------------
__device__ __forceinline__ const float* msg_ptr(
    const float* KVM, int u, int g, int n, float* w)
{
    if (u == 0) { *w = 6.f; return KVM + ((size_t)(g * 256 + n)) * 1024; }
    if (u <= 2) { *w = 6.f;
        return KVM + 524288u + (size_t)(u - 1) * 1048576u + ((size_t)(g * 256 + n)) * 1024; }
    int j = 1 + ((u - 3) >> 2), t = (u - 3) & 3;
    int type = t >> 1, gpp = t & 1;
    *w = 3.f;
    return KVM + 524288u + ((size_t)(j * 2 + type)) * 1048576u
         + ((size_t)((gpp * 2 + g) * 256 + n)) * 1024;
}

__global__ __launch_bounds__(256) void res_attn_kernel(
    const float* __restrict__ Qr, int ldq, int qmask,
    const float* __restrict__ KVM, int Mu,
    __nv_bfloat16* __restrict__ Oh, __nv_bfloat16* __restrict__ Ol)
{
    const int r = blockIdx.x;
    const int g = r >> 9;
    const int n = r & 255;
    const int qrow = r & qmask;

    const int tid  = threadIdx.x;
    const int h    = tid >> 5;
    const int lane = tid & 31;

    __shared__ float qs[512];
    __shared__ float sim[8][16];

    qs[tid]       = Qr[(size_t)qrow * ldq + tid];
    qs[tid + 256] = Qr[(size_t)qrow * ldq + tid + 256];
    __syncthreads();

    float sc = -1e30f;
    float wl = 0.f;
    if (lane < Mu) {
        const float* kpl = msg_ptr(KVM, lane, g, n, &wl);
        const float4* k4 = reinterpret_cast<const float4*>(kpl + h * 64);
        const float4* q4 = reinterpret_cast<const float4*>(&qs[h * 64]);
        float s = 0.f;
#pragma unroll
        for (int t = 0; t < 16; t++) {
            float4 kk = k4[t];
            float4 qq = q4[t];
            s += qq.x * kk.x + qq.y * kk.y + qq.z * kk.z + qq.w * kk.w;
        }
        sc = s;
    }
    float mx = sc;
#pragma unroll
    for (int o = 16; o > 0; o >>= 1) mx = fmaxf(mx, __shfl_xor_sync(0xffffffffu, mx, o));
    float p = (lane < Mu) ? wl * __expf(sc - mx) : 0.f;
    if (lane < 16) sim[h][lane] = p;
    float ls = p;
#pragma unroll
    for (int o = 16; o > 0; o >>= 1) ls += __shfl_xor_sync(0xffffffffu, ls, o);
    __syncwarp();

    float o0 = 0.f, o1 = 0.f;
    for (int u = 0; u < Mu; u++) {
        float a = sim[h][u];
        float dummy;
        const float* vp = msg_ptr(KVM, u, g, n, &dummy) + 512;
        o0 += a * vp[h * 64 + lane];
        o1 += a * vp[h * 64 + lane + 32];
    }
    float inv = 1.0f / ls;
    __nv_bfloat16 hh, ll;
    split_bf16(o0 * inv, hh, ll);
    Oh[(size_t)r * 512 + h * 64 + lane] = hh;
    Ol[(size_t)r * 512 + h * 64 + lane] = ll;
    split_bf16(o1 * inv, hh, ll);
    Oh[(size_t)r * 512 + h * 64 + lane + 32] = hh;
    Ol[(size_t)r * 512 + h * 64 + lane + 32] = ll;
}

// ---------------- init: tokens -> compressed T (dup over g) ----------------
__global__ void init_tok(const float* __restrict__ tokens,
                         float* __restrict__ T,
                         __nv_bfloat16* __restrict__ Th, __nv_bfloat16* __restrict__ Tl)
{
    int idx = blockIdx.x * blockDim.x + threadIdx.x;
    if (idx >= CROWS * DIM) return;
    int d = idx & 511;
    int r = idx >> 9;
    int n = r & 255;
    int b = (r >> 8) & 1;
    float v = tokens[((size_t)(b * 256 + n)) * 512 + d];
    T[idx] = v;
    __nv_bfloat16 h, l;
    split_bf16(v, h, l);
    Th[idx] = h; Tl[idx] = l;
}

// ---------------- fused weight preparation ----------------
// Wbig FF rows interleaved: row 512+2e = sim_e, row 512+2e+1 = gate_e.
#define SEG0 1923072               // wbig: NBIG*512
#define SEG1 (SEG0 + 524288)       // wkv
#define SEG2 (SEG1 + 524288)       // rkv
#define SEG3 (SEG2 + 262144)       // rwo
#define SEG4 (SEG3 + 262144)       // woT
#define SEG5 (SEG4 + 720896)       // wvpT: [1408,512]
#define SEG6 (SEG5 + NBIG)         // bias
__global__ void prep_all(
    const float* __restrict__ wq, const float* __restrict__ ffk,
    const float* __restrict__ rq,
    const float* __restrict__ anw, const float* __restrict__ fnw,
    const float* __restrict__ rnw,
    const float* __restrict__ wkv, const float* __restrict__ rkv,
    const float* __restrict__ rwo, const float* __restrict__ wo,
    const float* __restrict__ wvals, const float* __restrict__ ffb,
    __nv_bfloat16* __restrict__ Wbigh, __nv_bfloat16* __restrict__ Wbigl,
    __nv_bfloat16* __restrict__ Wkvh,  __nv_bfloat16* __restrict__ Wkvl,
    __nv_bfloat16* __restrict__ Rkvh,  __nv_bfloat16* __restrict__ Rkvl,
    __nv_bfloat16* __restrict__ Rwoh,  __nv_bfloat16* __restrict__ Rwol,
    __nv_bfloat16* __restrict__ WoTh,  __nv_bfloat16* __restrict__ WoTl,
    __nv_bfloat16* __restrict__ WvpTh, __nv_bfloat16* __restrict__ WvpTl,
    float* __restrict__ bias)
{
    int idx = blockIdx.x * 256 + threadIdx.x;
    if (idx >= SEG6) return;
    __nv_bfloat16 h, l;
    if (idx < SEG0) {
        int row = idx >> 9, k = idx & 511;
        float v = 0.f;
        if (row < 512)            v = wq [(size_t)row * 512 + k] * anw[k];
        else if (row < QRES_OFF) {
            int i = row - 512;
            int e = i >> 1, odd = i & 1;
            int src = odd ? (DFF + e) : e;
            v = ffk[(size_t)src * 512 + k] * fnw[k];
        }
        else if (row < 3754)      v = rq [(size_t)(row - QRES_OFF) * 512 + k] * rnw[k];
        split_bf16(v, h, l);
        Wbigh[idx] = h; Wbigl[idx] = l;
    } else if (idx < SEG1) {
        int i = idx - SEG0;
        split_bf16(wkv[i], h, l);
        Wkvh[i] = h; Wkvl[i] = l;
    } else if (idx < SEG2) {
        int i = idx - SEG1;
        split_bf16(rkv[i], h, l);
        Rkvh[i] = h; Rkvl[i] = l;
    } else if (idx < SEG3) {
        int i = idx - SEG2;
        split_bf16(rwo[i], h, l);
        Rwoh[i] = h; Rwol[i] = l;
    } else if (idx < SEG4) {
        int i = idx - SEG3;
        int e = i >> 9, d = i & 511;
        split_bf16(wo[(size_t)d * 512 + e], h, l);
        WoTh[i] = h; WoTl[i] = l;
    } else if (idx < SEG5) {
        int i = idx - SEG4;
        int e = i >> 9, d = i & 511;      // WvpT[e,d] = wvals[d, e]
        float v = (e < DFF) ? wvals[(size_t)d * DFF + e] : 0.f;
        split_bf16(v, h, l);
        WvpTh[i] = h; WvpTl[i] = l;
    } else {
        int i = idx - SEG5;
        float v = 0.f;
        if (i >= 512 && i < QRES_OFF) {
            int j = i - 512;
            int e = j >> 1, odd = j & 1;
            v = ffb[odd ? (DFF + e) : e];
        }
        bias[i] = v;
    }
}

// bret[c] = sum_d ff_values_b[d] * res_wkv[c,d]; warp per c.
__global__ __launch_bounds__(256) void bret_fill(
    const float* __restrict__ rkv, const float* __restrict__ fvb,
    float* __restrict__ bret)
{
    int c    = blockIdx.x * 8 + (threadIdx.x >> 5);
    int lane = threadIdx.x & 31;
    const float* rp = rkv + (size_t)c * 512;
    float s = 0.f;
#pragma unroll
    for (int t = 0; t < 16; t++) s += rp[lane + t * 32] * fvb[lane + t * 32];
#pragma unroll
    for (int o = 16; o > 0; o >>= 1) s += __shfl_xor_sync(0xffffffffu, s, o);
    if (lane == 0) bret[c] = s;
}

// -------------------------------- launch --------------------------------------
static float* s_part = nullptr;

static inline GTask mk_task(const __nv_bfloat16* Ah, const __nv_bfloat16* Al, int lda,
                            const __nv_bfloat16* Bh, const __nv_bfloat16* Bl,
                            const float* bias, float* Yf,
                            __nv_bfloat16* Yh, __nv_bfloat16* Yl,
                            int M, int N, int K, int mode)
{
    GTask t;
    t.Ah = Ah; t.Al = Al; t.Bh = Bh; t.Bl = Bl; t.bias = bias;
    t.Yf = Yf; t.Yh = Yh; t.Yl = Yl;
    t.lda = lda; t.M = M; t.N = N; t.K = K; t.mode = mode;
    t.nx = (N + 63) / 64;
    t.nblocks = t.nx * (M / 128);
    return t;
}
static inline GTask empty_task() { GTask t = {}; t.nblocks = 0; t.nx = 1; return t; }

static inline void launch_group(GTask a, GTask b, GTask c)
{
    int total = a.nblocks + b.nblocks + c.nblocks;
    gemm_group<<<total, GTHREADS, GSMEM>>>(a, b, c);
}

extern "C" void kernel_launch(void* const* d_in, const int* in_sizes, int n_in,
                              void* d_out, int out_size)
{
    const float* tokens      = (const float*)d_in[0];
    const float* attn_norm_w = (const float*)d_in[1];
    const float* attn_wq     = (const float*)d_in[2];
    const float* attn_wkv    = (const float*)d_in[3];
    const float* attn_wo     = (const float*)d_in[4];
    const float* ff_norm_w   = (const float*)d_in[5];
    const float* ff_keys_w   = (const float*)d_in[6];
    const float* ff_keys_b   = (const float*)d_in[7];
    const float* ff_values_w = (const float*)d_in[8];
    const float* ff_values_b = (const float*)d_in[9];
    const float* res_norm_w  = (const float*)d_in[10];
    const float* res_wq      = (const float*)d_in[11];
    const float* res_wkv     = (const float*)d_in[12];
    const float* res_wo      = (const float*)d_in[13];
    float* out = (float*)d_out;

    cudaFuncSetAttribute(gemm_mma,   cudaFuncAttributeMaxDynamicSharedMemorySize, GSMEM);
    cudaFuncSetAttribute(gemm_group, cudaFuncAttributeMaxDynamicSharedMemorySize, GSMEM);

    float *B, *T, *KV, *kvm, *bias, *bret, *pacc, *pml;
    __nv_bfloat16 *XNh, *XNl, *XAh, *XAl, *ACTh, *ACTl, *XRh, *XRl, *Th, *Tl;
    __nv_bfloat16 *Wbigh, *Wbigl, *Wkvh, *Wkvl, *Rkvh, *Rkvl, *WoTh, *WoTl;
    __nv_bfloat16 *WvpTh, *WvpTl, *Rwoh, *Rwol, *Cath, *Catl, *Creth, *Cretl;
    cudaGetSymbolAddress((void**)&B,    g_B);
    cudaGetSymbolAddress((void**)&T,    g_T);
    cudaGetSymbolAddress((void**)&KV,   g_KV);
    cudaGetSymbolAddress((void**)&kvm,  g_kvm);
    cudaGetSymbolAddress((void**)&bias, g_bias);
    cudaGetSymbolAddress((void**)&bret, g_bret);
    cudaGetSymbolAddress((void**)&pacc, g_pacc);
    cudaGetSymbolAddress((void**)&pml,  g_pml);
    cudaGetSymbolAddress((void**)&s_part, g_part);
    cudaGetSymbolAddress((void**)&XNh,  g_XNh);  cudaGetSymbolAddress((void**)&XNl, g_XNl);
    cudaGetSymbolAddress((void**)&XAh,  g_XAh);  cudaGetSymbolAddress((void**)&XAl, g_XAl);
    cudaGetSymbolAddress((void**)&ACTh, g_ACTh); cudaGetSymbolAddress((void**)&ACTl, g_ACTl);
    cudaGetSymbolAddress((void**)&XRh,  g_XRh);  cudaGetSymbolAddress((void**)&XRl, g_XRl);
    cudaGetSymbolAddress((void**)&Th,   g_Th);   cudaGetSymbolAddress((void**)&Tl,  g_Tl);
    cudaGetSymbolAddress((void**)&Wbigh, g_Wbigh); cudaGetSymbolAddress((void**)&Wbigl, g_Wbigl);
    cudaGetSymbolAddress((void**)&Wkvh, g_Wkvh); cudaGetSymbolAddress((void**)&Wkvl, g_Wkvl);
    cudaGetSymbolAddress((void**)&Rkvh, g_Rkvh); cudaGetSymbolAddress((void**)&Rkvl, g_Rkvl);
    cudaGetSymbolAddress((void**)&WoTh, g_WoTh); cudaGetSymbolAddress((void**)&WoTl, g_WoTl);
    cudaGetSymbolAddress((void**)&WvpTh, g_WvpTh); cudaGetSymbolAddress((void**)&WvpTl, g_WvpTl);
    cudaGetSymbolAddress((void**)&Rwoh, g_Rwoh); cudaGetSymbolAddress((void**)&Rwol, g_Rwol);
    cudaGetSymbolAddress((void**)&Cath, g_Cath); cudaGetSymbolAddress((void**)&Catl, g_Catl);
    cudaGetSymbolAddress((void**)&Creth, g_Creth); cudaGetSymbolAddress((void**)&Cretl, g_Cretl);

    // prologue: weight prep + token init + bret
    init_tok<<<(CROWS * DIM + 255) / 256, 256>>>(tokens, T, Th, Tl);
    prep_all<<<(SEG6 + 255) / 256, 256>>>(
        attn_wq, ff_keys_w, res_wq, attn_norm_w, ff_norm_w, res_norm_w,
        attn_wkv, res_wkv, res_wo, attn_wo, ff_values_w, ff_keys_b,
        Wbigh, Wbigl, Wkvh, Wkvl, Rkvh, Rkvl, Rwoh, Rwol,
        WoTh, WoTl, WvpTh, WvpTl, bias);
    bret_fill<<<128, 256>>>(res_wkv, ff_values_b, bret);

    // grouped prologue GEMMs: C_att, Cret, tokens-kv
    launch_group(
        mk_task(Rkvh, Rkvl, 512, WoTh, WoTl, nullptr, nullptr, Cath, Catl,
                1024, 512, 512, 0),
        mk_task(Rkvh, Rkvl, 512, WvpTh, WvpTl, nullptr, nullptr, Creth, Cretl,
                1024, DFFP, 512, 0),
        mk_task(Th, Tl, 512, Rkvh, Rkvl, nullptr, kvm, nullptr, nullptr,
                512, 1024, 512, 0));

    for (int e = 0; e < 3; e++) {
        const int Mr = (e == 0) ? 512 : 1024;     // e0 is g-degenerate
        const int nb = Mr >> 8;
        float* kv_att = kvm + 524288 + (size_t)(e * 2 + 0) * 1048576;
        float* kv_ret = kvm + 524288 + (size_t)(e * 2 + 1) * 1048576;

        // e0: norm from init tokens; e1/e2: XN already produced by combine_rms
        if (e == 0)
            rmsnorm_now<<<Mr / 8, 256>>>(T, XNh, XNl, Mr);

        // GA: mega (fused geglu) + self-attn KV projection
        launch_group(
            mk_task(XNh, XNl, 512, Wbigh, Wbigl, bias, B, ACTh, ACTl,
                    Mr, NBIG, 512, 1),
            mk_task(Th, Tl, 512, Wkvh, Wkvl, nullptr, KV, nullptr, nullptr,
                    Mr, 1024, 512, 0),
            empty_task());

        self_attn_part<<<dim3(HEADS, nb, 4), 256>>>(B, NBIG, KV, pacc, pml, nb);
        self_attn_combine<<<nb * 8, 256>>>(pacc, pml, XAh, XAl, nb);

        // GB: attended kv (WO folded) + retrieved kv (FFV+RKV folded via Cret)
        launch_group(
            mk_task(XAh, XAl, 512, Cath, Catl, nullptr, kv_att, nullptr, nullptr,
                    Mr, 1024, 512, 0),
            mk_task(ACTh, ACTl, DFFP, Creth, Cretl, bret, kv_ret, nullptr, nullptr,
                    Mr, 1024, DFFP, 0),
            empty_task());

        // residual pooled attention over unique messages
        res_attn_kernel<<<CROWS, 256>>>(B + QRES_OFF, NBIG, (e == 0) ? 511 : 1023,
                                        kvm, 3 + 4 * e, XRh, XRl);

        // rwo GEMM via split-K (CROWS x 512 x 512, 32 base blocks -> s=4)
        {
            dim3 grid(8, CROWS / 128, 4);
            gemm_mma<<<grid, GTHREADS, GSMEM>>>(XRh, XRl, 512, Rwoh, Rwol, nullptr,
                                                nullptr, nullptr, nullptr,
                                                CROWS, 512, 512, 4, s_part, 0);
            if (e == 2) {
                int MN = CROWS * 512;
                splitk_combine<<<(MN / 2 + 255) / 256, 256>>>(
                    s_part, 4, MN, 512, nullptr, nullptr, nullptr, nullptr, out);
            } else {
                combine_rms<<<CROWS, 256>>>(s_part, 4, T, Th, Tl, XNh, XNl);
            }
        }
    }
}

// round 16
// speedup vs baseline: 1.0429x; 1.0429x over previous
#include <cuda_runtime.h>
#include <cuda_bf16.h>
#include <math.h>
#include <stdint.h>

#define DIM     512
#define HEADS   8
#define DFF     1365
#define DFFP    1408            // DFF padded (K multiple of 32)
#define CROWS   1024            // compressed rows: (g,b,n)
#define NBIG    3756            // 512 + 2730 + 512 + 2 align pad
#define QRES_OFF 3242           // 512 + 2730
#define RMS_EPS 1.1920929e-07f

// ---------------- scratch (device globals) ----------------
static __device__ float g_B   [CROWS * NBIG];     // [Q | (ff unused) | Qres]
static __device__ float g_T   [CROWS * DIM];
static __device__ float g_KV  [CROWS * 1024];
static __device__ float g_kvm [512 * 1024 + 6 * 1024 * 1024]; // tok + (att,ret)x3
static __device__ float g_bias[NBIG];
static __device__ float g_bret[1024];
static __device__ float g_pacc[128 * 64 * 256];
static __device__ float g_pml [128 * 2 * 256];
static __device__ float g_part[1 << 21];          // split-K partials

static __device__ __nv_bfloat16 g_XNh[CROWS * DIM],  g_XNl[CROWS * DIM];
static __device__ __nv_bfloat16 g_XAh[CROWS * DIM],  g_XAl[CROWS * DIM];
static __device__ __nv_bfloat16 g_ACTh[CROWS * DFFP], g_ACTl[CROWS * DFFP]; // pad cols stay 0
static __device__ __nv_bfloat16 g_XRh[CROWS * DIM],  g_XRl[CROWS * DIM];
static __device__ __nv_bfloat16 g_Th [CROWS * DIM],  g_Tl [CROWS * DIM];

static __device__ __nv_bfloat16 g_Wbigh[NBIG * 512], g_Wbigl[NBIG * 512];
static __device__ __nv_bfloat16 g_Wkvh[1024 * 512],  g_Wkvl[1024 * 512];
static __device__ __nv_bfloat16 g_Rkvh[1024 * 512],  g_Rkvl[1024 * 512];
static __device__ __nv_bfloat16 g_WoTh[512 * 512],   g_WoTl[512 * 512];
static __device__ __nv_bfloat16 g_WvpTh[DFFP * 512], g_WvpTl[DFFP * 512];
static __device__ __nv_bfloat16 g_Rwoh[512 * 512],   g_Rwol[512 * 512];
static __device__ __nv_bfloat16 g_Cath[1024 * 512],  g_Catl[1024 * 512];
static __device__ __nv_bfloat16 g_Creth[1024 * DFFP], g_Cretl[1024 * DFFP];

// ---------------- helpers ----------------
__device__ __forceinline__ void split_bf16(float v, __nv_bfloat16& h, __nv_bfloat16& l) {
    h = __float2bfloat16(v);
    l = __float2bfloat16(v - __bfloat162float(h));
}
__device__ __forceinline__ uint32_t smem_u32(const void* p) {
    uint32_t a;
    asm("{ .reg .u64 t; cvta.to.shared.u64 t, %1; cvt.u32.u64 %0, t; }" : "=r"(a) : "l"(p));
    return a;
}
__device__ __forceinline__ void cp16(uint32_t dst, const void* src, uint32_t sz) {
    asm volatile("cp.async.cg.shared.global [%0], [%1], 16, %2;"
                 :: "r"(dst), "l"(src), "r"(sz));
}
__device__ __forceinline__ void ldsm4(uint32_t& r0, uint32_t& r1, uint32_t& r2,
                                      uint32_t& r3, uint32_t addr) {
    asm volatile("ldmatrix.sync.aligned.m8n8.x4.shared.b16 {%0,%1,%2,%3}, [%4];"
                 : "=r"(r0), "=r"(r1), "=r"(r2), "=r"(r3) : "r"(addr));
}
__device__ __forceinline__ void mma16816(float* c, const uint32_t* a, const uint32_t* b) {
    asm volatile(
        "mma.sync.aligned.m16n8k16.row.col.f32.bf16.bf16.f32 "
        "{%0,%1,%2,%3}, {%4,%5,%6,%7}, {%8,%9}, {%0,%1,%2,%3};"
        : "+f"(c[0]), "+f"(c[1]), "+f"(c[2]), "+f"(c[3])
        : "r"(a[0]), "r"(a[1]), "r"(a[2]), "r"(a[3]), "r"(b[0]), "r"(b[1]));
}
__device__ __forceinline__ float gelu_pair(float sim, float gate) {
    return sim * (0.5f * gate * (1.0f + erff(gate * 0.70710678118654752440f)));
}

// ---------------- GEMM core (split-bf16, 3-stage cp.async; R11 config) ----------
// 128x64 block tile, 256 threads = 8 warps of 32x32 (4M x 2N layout).
#define GSTAGE   30720
#define GSMEM    (3 * GSTAGE)
#define GTHREADS 256

__device__ __forceinline__ void g_loads(
    uint32_t sb, int tid, int buf, int ck,
    const __nv_bfloat16* Ah, const __nv_bfloat16* Al, int lda,
    const __nv_bfloat16* Bh, const __nv_bfloat16* Bl,
    int K, int N, int bm0, int bn0)
{
    const uint32_t bufbase = sb + (uint32_t)buf * GSTAGE;
#pragma unroll
    for (int i = 0; i < 6; i++) {
        int c = tid + i * GTHREADS;
        int R = c >> 2;
        int q = c & 3;
        uint32_t dst = bufbase + (uint32_t)R * 80u + (uint32_t)q * 16u;
        const __nv_bfloat16* src;
        uint32_t sz = 16;
        if (R < 256) {
            src = (R < 128 ? Ah : Al) + (size_t)(bm0 + (R & 127)) * lda;
        } else {
            int rg = bn0 + (R & 63);
            if (rg >= N) { rg = 0; sz = 0; }
            src = (R < 320 ? Bh : Bl) + (size_t)rg * K;
        }
        cp16(dst, src + ck * 32 + q * 8, sz);
    }
    asm volatile("cp.async.commit_group;");
}

__device__ __forceinline__ void gemm_core(
    const __nv_bfloat16* Ah, const __nv_bfloat16* Al, int lda,
    const __nv_bfloat16* Bh, const __nv_bfloat16* Bl,
    const float* bias, float* Yf, __nv_bfloat16* Yh, __nv_bfloat16* Yl,
    int M, int N, int K, int splitk, float* Pf, int mode,
    int bn0, int bm0, int z)
{
    extern __shared__ __align__(16) char smem[];
    const uint32_t sb = smem_u32(smem);
    const int tid  = threadIdx.x;
    const int wid  = tid >> 5;
    const int lane = tid & 31;
    const int m0w  = (wid & 3) * 32;
    const int n0w  = (wid >> 2) * 32;

    float C[2][4][4];
#pragma unroll
    for (int mt = 0; mt < 2; mt++)
#pragma unroll
        for (int nt = 0; nt < 4; nt++)
#pragma unroll
            for (int v = 0; v < 4; v++) C[mt][nt][v] = 0.f;

    uint32_t aoffH[2], aoffL[2], boffH[2], boffL[2];
#pragma unroll
    for (int mt = 0; mt < 2; mt++) {
        uint32_t row = (uint32_t)(m0w + mt * 16 + (lane & 15));
        uint32_t kb  = (uint32_t)((lane >> 4) * 16);
        aoffH[mt] = sb + row * 80u + kb;
        aoffL[mt] = aoffH[mt] + 10240u;
    }
#pragma unroll
    for (int bt = 0; bt < 2; bt++) {
        uint32_t row = (uint32_t)(n0w + bt * 16 + (lane & 7) + ((lane >> 4) << 3));
        uint32_t kb  = (uint32_t)(((lane >> 3) & 1) * 16);
        boffH[bt] = sb + 20480u + row * 80u + kb;
        boffL[bt] = boffH[bt] + 5120u;
    }

    const int kspan = K / splitk;
    const int nk    = kspan >> 5;
    const int kb32  = z * nk;
    g_loads(sb, tid, 0, kb32 + 0, Ah, Al, lda, Bh, Bl, K, N, bm0, bn0);
    g_loads(sb, tid, 1, kb32 + 1, Ah, Al, lda, Bh, Bl, K, N, bm0, bn0);

    int buf = 0;
    for (int t = 0; t < nk; t++) {
        if (t < nk - 1) asm volatile("cp.async.wait_group 1;" ::: "memory");
        else            asm volatile("cp.async.wait_group 0;" ::: "memory");
        __syncthreads();

        if (t + 2 < nk) {
            int lb = buf + 2; if (lb >= 3) lb -= 3;
            g_loads(sb, tid, lb, kb32 + t + 2, Ah, Al, lda, Bh, Bl, K, N, bm0, bn0);
        }

        const uint32_t bofs = (uint32_t)buf * GSTAGE;
#pragma unroll
        for (int ks = 0; ks < 2; ks++) {
            const uint32_t ko = bofs + (uint32_t)ks * 32u;
            uint32_t ah[2][4], al[2][4], bh[4][2], bl[4][2];
#pragma unroll
            for (int mt = 0; mt < 2; mt++) {
                ldsm4(ah[mt][0], ah[mt][1], ah[mt][2], ah[mt][3], aoffH[mt] + ko);
                ldsm4(al[mt][0], al[mt][1], al[mt][2], al[mt][3], aoffL[mt] + ko);
            }
            ldsm4(bh[0][0], bh[0][1], bh[1][0], bh[1][1], boffH[0] + ko);
            ldsm4(bh[2][0], bh[2][1], bh[3][0], bh[3][1], boffH[1] + ko);
            ldsm4(bl[0][0], bl[0][1], bl[1][0], bl[1][1], boffL[0] + ko);
            ldsm4(bl[2][0], bl[2][1], bl[3][0], bl[3][1], boffL[1] + ko);
#pragma unroll
            for (int mt = 0; mt < 2; mt++)
#pragma unroll
                for (int nt = 0; nt < 4; nt++) {
                    mma16816(C[mt][nt], ah[mt], bh[nt]);
                    mma16816(C[mt][nt], ah[mt], bl[nt]);
                    mma16816(C[mt][nt], al[mt], bh[nt]);
                }
        }
        buf = (buf == 2) ? 0 : buf + 1;
    }

    if (splitk > 1) {
        float* P = Pf + (size_t)z * M * N;
#pragma unroll
        for (int mt = 0; mt < 2; mt++) {
            const int row = bm0 + m0w + mt * 16 + (lane >> 2);
#pragma unroll
            for (int nt = 0; nt < 4; nt++) {
                const int col = bn0 + n0w + nt * 8 + (lane & 3) * 2;
                if (col < N) {
                    *reinterpret_cast<float2*>(P + (size_t)row * N + col)
                        = make_float2(C[mt][nt][0], C[mt][nt][1]);
                    *reinterpret_cast<float2*>(P + (size_t)(row + 8) * N + col)
                        = make_float2(C[mt][nt][2], C[mt][nt][3]);
                }
            }
        }
        return;
    }

#pragma unroll
    for (int mt = 0; mt < 2; mt++) {
        const int row = bm0 + m0w + mt * 16 + (lane >> 2);
#pragma unroll
        for (int nt = 0; nt < 4; nt++) {
            const int col = bn0 + n0w + nt * 8 + (lane & 3) * 2;
            if (col < N) {
                float b0 = bias ? bias[col]     : 0.f;
                float b1 = bias ? bias[col + 1] : 0.f;
                float v00 = C[mt][nt][0] + b0, v01 = C[mt][nt][1] + b1;
                float v10 = C[mt][nt][2] + b0, v11 = C[mt][nt][3] + b1;
                if (mode == 1) {
                    if (col >= 512 && col < QRES_OFF) {
                        int e = (col - 512) >> 1;
                        float a0 = gelu_pair(v00, v01);
                        float a1 = gelu_pair(v10, v11);
                        __nv_bfloat16 h, l;
                        split_bf16(a0, h, l);
                        Yh[(size_t)row * DFFP + e] = h;
                        Yl[(size_t)row * DFFP + e] = l;
                        split_bf16(a1, h, l);
                        Yh[(size_t)(row + 8) * DFFP + e] = h;
                        Yl[(size_t)(row + 8) * DFFP + e] = l;
                    } else {
                        *reinterpret_cast<float2*>(Yf + (size_t)row * N + col)
                            = make_float2(v00, v01);
                        *reinterpret_cast<float2*>(Yf + (size_t)(row + 8) * N + col)
                            = make_float2(v10, v11);
                    }
                    continue;
                }
                const size_t o0 = (size_t)row * N + col;
                const size_t o1 = (size_t)(row + 8) * N + col;
                if (Yf) {
                    *reinterpret_cast<float2*>(Yf + o0) = make_float2(v00, v01);
                    *reinterpret_cast<float2*>(Yf + o1) = make_float2(v10, v11);
                }
                if (Yh) {
                    __nv_bfloat16 h0, l0, h1, l1;
                    split_bf16(v00, h0, l0); split_bf16(v01, h1, l1);
                    *reinterpret_cast<__nv_bfloat162*>(Yh + o0) = __nv_bfloat162(h0, h1);
                    *reinterpret_cast<__nv_bfloat162*>(Yl + o0) = __nv_bfloat162(l0, l1);
                    split_bf16(v10, h0, l0); split_bf16(v11, h1, l1);
                    *reinterpret_cast<__nv_bfloat162*>(Yh + o1) = __nv_bfloat162(h0, h1);
                    *reinterpret_cast<__nv_bfloat162*>(Yl + o1) = __nv_bfloat162(l0, l1);
                }
            }
        }
    }
}

// ---------------- single-task GEMM (supports split-K) ----------------
__global__ __launch_bounds__(GTHREADS) void gemm_mma(
    const __nv_bfloat16* __restrict__ Ah, const __nv_bfloat16* __restrict__ Al, int lda,
    const __nv_bfloat16* __restrict__ Bh, const __nv_bfloat16* __restrict__ Bl,
    const float* __restrict__ bias,
    float* __restrict__ Yf, __nv_bfloat16* __restrict__ Yh, __nv_bfloat16* __restrict__ Yl,
    int M, int N, int K, int splitk, float* __restrict__ Pf, int mode)
{
    gemm_core(Ah, Al, lda, Bh, Bl, bias, Yf, Yh, Yl, M, N, K, splitk, Pf, mode,
              blockIdx.x * 64, blockIdx.y * 128, blockIdx.z);
}

// ---------------- grouped GEMM (contiguous task ranges; R14 version) ------------
struct GTask {
    const __nv_bfloat16 *Ah, *Al, *Bh, *Bl;
    const float* bias;
    float* Yf;
    __nv_bfloat16 *Yh, *Yl;
    int lda, M, N, K, mode, nx, nblocks;
};

__global__ __launch_bounds__(GTHREADS) void gemm_group(GTask t0, GTask t1, GTask t2)
{
    int bx = blockIdx.x;
    GTask t;
    if (bx < t0.nblocks) { t = t0; }
    else if (bx < t0.nblocks + t1.nblocks) { t = t1; bx -= t0.nblocks; }
    else { t = t2; bx -= t0.nblocks + t1.nblocks; }
    int bn0 = (bx % t.nx) * 64;
    int bm0 = (bx / t.nx) * 128;
    gemm_core(t.Ah, t.Al, t.lda, t.Bh, t.Bl, t.bias, t.Yf, t.Yh, t.Yl,
              t.M, t.N, t.K, 1, nullptr, t.mode, bn0, bm0, 0);
}

// ---------------- split-K combine (optional expanded fanout output) -------------
__global__ __launch_bounds__(256) void splitk_combine(
    const float* __restrict__ P, int parts, int MN, int N,
    const float* __restrict__ bias,
    float* __restrict__ Yf,
    __nv_bfloat16* __restrict__ Yh, __nv_bfloat16* __restrict__ Yl,
    float* __restrict__ Yexp)
{
    int idx = (blockIdx.x * 256 + threadIdx.x) * 2;
    if (idx >= MN) return;
    float2 a = *reinterpret_cast<const float2*>(P + idx);
    for (int p = 1; p < parts; p++) {
        float2 b = *reinterpret_cast<const float2*>(P + (size_t)p * MN + idx);
        a.x += b.x; a.y += b.y;
    }
    if (bias) {
        int col = idx % N;
        a.x += bias[col];
        a.y += bias[col + 1];
    }
    if (Yexp) {
        int row = idx / N;
        int col = idx - row * N;
        int g   = row >> 9;
        int rem = row & 511;
#pragma unroll
        for (int j = 0; j < 3; j++) {
            int r2 = ((3 * g + j) << 9) + rem;
            *reinterpret_cast<float2*>(Yexp + (size_t)r2 * N + col) = a;
        }
        return;
    }
    if (Yf) *reinterpret_cast<float2*>(Yf + idx) = a;
    if (Yh) {
        __nv_bfloat16 h0, l0, h1, l1;
        split_bf16(a.x, h0, l0); split_bf16(a.y, h1, l1);
        *reinterpret_cast<__nv_bfloat162*>(Yh + idx) = __nv_bfloat162(h0, h1);
        *reinterpret_cast<__nv_bfloat162*>(Yl + idx) = __nv_bfloat162(l0, l1);
    }
}

// ---------------- fused split-K combine + RMSNorm (block per 512-col row) -------
__global__ __launch_bounds__(256) void combine_rms(
    const float* __restrict__ P, int parts,
    float* __restrict__ T,
    __nv_bfloat16* __restrict__ Th, __nv_bfloat16* __restrict__ Tl,
    __nv_bfloat16* __restrict__ XNh, __nv_bfloat16* __restrict__ XNl)
{
    const int row = blockIdx.x;
    const int tid = threadIdx.x;
    const int idx = row * DIM + tid * 2;
    const int MN  = CROWS * DIM;

    __shared__ float red[8];

    float2 a = *reinterpret_cast<const float2*>(P + idx);
    for (int p = 1; p < parts; p++) {
        float2 b = *reinterpret_cast<const float2*>(P + (size_t)p * MN + idx);
        a.x += b.x; a.y += b.y;
    }

    *reinterpret_cast<float2*>(T + idx) = a;
    __nv_bfloat16 h0, l0, h1, l1;
    split_bf16(a.x, h0, l0); split_bf16(a.y, h1, l1);
    *reinterpret_cast<__nv_bfloat162*>(Th + idx) = __nv_bfloat162(h0, h1);
    *reinterpret_cast<__nv_bfloat162*>(Tl + idx) = __nv_bfloat162(l0, l1);

    float ss = a.x * a.x + a.y * a.y;
#pragma unroll
    for (int o = 16; o > 0; o >>= 1) ss += __shfl_xor_sync(0xffffffffu, ss, o);
    if ((tid & 31) == 0) red[tid >> 5] = ss;
    __syncthreads();
    if (tid < 8) {
        float v = red[tid];
#pragma unroll
        for (int o = 4; o > 0; o >>= 1) v += __shfl_xor_sync(0xffu, v, o);
        if (tid == 0) red[0] = v;
    }
    __syncthreads();
    float rs = rsqrtf(red[0] * (1.0f / 512.0f) + RMS_EPS);

    split_bf16(a.x * rs, h0, l0); split_bf16(a.y * rs, h1, l1);
    *reinterpret_cast<__nv_bfloat162*>(XNh + idx) = __nv_bfloat162(h0, h1);
    *reinterpret_cast<__nv_bfloat162*>(XNl + idx) = __nv_bfloat162(l0, l1);
}

// ---------------- packed f32x2 helpers ----------------
__device__ __forceinline__ void ffma2(unsigned long long& d, unsigned long long a,
                                      unsigned long long b) {
    asm("fma.rn.f32x2 %0, %1, %2, %0;" : "+l"(d) : "l"(a), "l"(b));
}
__device__ __forceinline__ unsigned long long fma2_3(unsigned long long a,
                                                     unsigned long long b,
                                                     unsigned long long c) {
    unsigned long long d;
    asm("fma.rn.f32x2 %0, %1, %2, %3;" : "=l"(d) : "l"(a), "l"(b), "l"(c));
    return d;
}
__device__ __forceinline__ unsigned long long mul2(unsigned long long a,
                                                   unsigned long long b) {
    unsigned long long d;
    asm("mul.rn.f32x2 %0, %1, %2;" : "=l"(d) : "l"(a), "l"(b));
    return d;
}
__device__ __forceinline__ unsigned long long dup2(float x) {
    unsigned long long r;
    asm("mov.b64 %0, {%1, %1};" : "=l"(r) : "f"(x));
    return r;
}
__device__ __forceinline__ unsigned long long pk2(float x, float y) {
    unsigned long long r;
    asm("mov.b64 %0, {%1, %2};" : "=l"(r) : "f"(x), "f"(y));
    return r;
}
__device__ __forceinline__ float2 unpack2(unsigned long long v) {
    float2 f;
    asm("mov.b64 {%0, %1}, %2;" : "=f"(f.x), "=f"(f.y) : "l"(v));
    return f;
}

// ---------------- RMSNorm (used only for exchange 0 on init tokens) -------------
__global__ __launch_bounds__(256) void rmsnorm_now(
    const float* __restrict__ X,
    __nv_bfloat16* __restrict__ Yh, __nv_bfloat16* __restrict__ Yl, int rows)
{
    int row  = blockIdx.x * 8 + (threadIdx.x >> 5);
    int lane = threadIdx.x & 31;
    if (row >= rows) return;
    const float* xp = X + (size_t)row * DIM;
    float x[16];
    float ss = 0.f;
#pragma unroll
    for (int t = 0; t < 16; t++) { x[t] = xp[lane + t * 32]; ss += x[t] * x[t]; }
#pragma unroll
    for (int o = 16; o > 0; o >>= 1) ss += __shfl_xor_sync(0xffffffffu, ss, o);
    float rs = rsqrtf(ss * (1.0f / 512.0f) + RMS_EPS);
#pragma unroll
    for (int t = 0; t < 16; t++) {
        int c = lane + t * 32;
        __nv_bfloat16 h, l;
        split_bf16(x[t] * rs, h, l);
        Yh[(size_t)row * DIM + c] = h;
        Yl[(size_t)row * DIM + c] = l;
    }
}

// ---------------- Self attention, split over 4 key-chunks ----------------
__global__ __launch_bounds__(256) void self_attn_part(
    const float* __restrict__ Q, int ldq, const float* __restrict__ KV,
    float* __restrict__ pacc, float* __restrict__ pml, int nbatch)
{
    const int h     = blockIdx.x;
    const int batch = blockIdx.y;
    const int jc    = blockIdx.z;
    const int i     = threadIdx.x;
    const int j0    = jc * 64;

    __shared__ __align__(16) float Ks[64][64];
    __shared__ __align__(16) float Vs[64][64];

    unsigned long long qp[32];
    {
        const float4* qq = reinterpret_cast<const float4*>(
            Q + ((size_t)(batch * 256 + i)) * ldq + h * 64);
#pragma unroll
        for (int t = 0; t < 16; t++) {
            float4 v = qq[t];
            qp[2 * t]     = pk2(v.x, v.y);
            qp[2 * t + 1] = pk2(v.z, v.w);
        }
    }

#pragma unroll
    for (int s = 0; s < 4; s++) {
        int u  = threadIdx.x + s * 256;
        int jr = u >> 4;
        int c4 = u & 15;
        const float* kp = KV + ((size_t)(batch * 256 + j0 + jr)) * 1024 + h * 64 + c4 * 4;
        *reinterpret_cast<float4*>(&Ks[jr][c4 * 4]) = *reinterpret_cast<const float4*>(kp);
        *reinterpret_cast<float4*>(&Vs[jr][c4 * 4]) = *reinterpret_cast<const float4*>(kp + 512);
    }
    __syncthreads();

    float m = -1e30f, l = 0.f;
    unsigned long long acc[32];
#pragma unroll
    for (int t = 0; t < 32; t++) acc[t] = 0ull;

    for (int j = 0; j < 64; j++) {
        const ulonglong2* kr = reinterpret_cast<const ulonglong2*>(Ks[j]);
        unsigned long long s0 = 0ull, s1 = 0ull;
#pragma unroll
        for (int t = 0; t < 8; t++) {
            ulonglong2 k0 = kr[2 * t];
            ulonglong2 k1 = kr[2 * t + 1];
            ffma2(s0, qp[4 * t + 0], k0.x);
            ffma2(s1, qp[4 * t + 1], k0.y);
            ffma2(s0, qp[4 * t + 2], k1.x);
            ffma2(s1, qp[4 * t + 3], k1.y);
        }
        float2 sa = unpack2(s0), sb = unpack2(s1);
        float s = (sa.x + sa.y) + (sb.x + sb.y);

        float mn = fmaxf(m, s);
        float f  = __expf(m - mn);
        float p  = __expf(s - mn);
        l = l * f + p;
        unsigned long long fd = dup2(f), pd = dup2(p);
        const ulonglong2* vr = reinterpret_cast<const ulonglong2*>(Vs[j]);
#pragma unroll
        for (int t = 0; t < 16; t++) {
            ulonglong2 vv = vr[t];
            acc[2 * t]     = fma2_3(acc[2 * t],     fd, mul2(vv.x, pd));
            acc[2 * t + 1] = fma2_3(acc[2 * t + 1], fd, mul2(vv.y, pd));
        }
        m = mn;
    }

    const int bl = (jc * nbatch + batch) * HEADS + h;
    float* pa = pacc + ((size_t)bl * 64) * 256;
#pragma unroll
    for (int t = 0; t < 32; t++) {
        float2 a = unpack2(acc[t]);
        pa[(2 * t) * 256 + i]     = a.x;
        pa[(2 * t + 1) * 256 + i] = a.y;
    }
    pml[(bl * 2 + 0) * 256 + i] = m;
    pml[(bl * 2 + 1) * 256 + i] = l;
}

__global__ __launch_bounds__(256) void self_attn_combine(
    const float* __restrict__ pacc, const float* __restrict__ pml,
    __nv_bfloat16* __restrict__ Oh, __nv_bfloat16* __restrict__ Ol, int nbatch)
{
    int idx   = blockIdx.x * 256 + threadIdx.x;
    int i     = idx & 255;
    int h     = (idx >> 8) & 7;
    int batch = idx >> 11;

    float mc[4], lc[4];
    float M = -1e30f;
#pragma unroll
    for (int c = 0; c < 4; c++) {
        int bl = (c * nbatch + batch) * HEADS + h;
        mc[c] = pml[(bl * 2 + 0) * 256 + i];
        lc[c] = pml[(bl * 2 + 1) * 256 + i];
        M = fmaxf(M, mc[c]);
    }
    float w[4];
    float L = 0.f;
#pragma unroll
    for (int c = 0; c < 4; c++) { w[c] = __expf(mc[c] - M); L += lc[c] * w[c]; }
    float inv = 1.0f / L;

    size_t ob = ((size_t)(batch * 256 + i)) * 512 + h * 64;
#pragma unroll
    for (int t = 0; t < 64; t++) {
        float o = 0.f;
#pragma unroll
        for (int c = 0; c < 4; c++) {
            int bl = (c * nbatch + batch) * HEADS + h;
            o += w[c] * pacc[((size_t)bl * 64 + t) * 256 + i];
        }
        __nv_bfloat16 hh, ll;
        split_bf16(o * inv, hh, ll);
        Oh[ob + t] = hh;
        Ol[ob + t] = ll;
    }
}

// ---------------- Residual attention over unique messages ----------------
__device__ __forceinline__ const float* msg_ptr(
    const float* KVM, int u, int g, int n, float* w)
{
    if (u == 0) { *w = 6.f; return KVM + ((size_t)(g * 256 + n)) * 1024; }
    if (u <= 2) { *w = 6.f;
        return KVM + 524288u + (size_t)(u - 1) * 1048576u + ((size_t)(g * 256 + n)) * 1024; }
    int j = 1 + ((u - 3) >> 2), t = (u - 3) & 3;
    int type = t >> 1, gpp = t & 1;
    *w = 3.f;
    return KVM + 524288u + ((size_t)(j * 2 + type)) * 1048576u
         + ((size_t)((gpp * 2 + g) * 256 + n)) * 1024;
}

__global__ __launch_bounds__(256) void res_attn_kernel(
    const float* __restrict__ Qr, int ldq, int qmask,
    const float* __restrict__ KVM, int Mu,
    __nv_bfloat16* __restrict__ Oh, __nv_bfloat16* __restrict__ Ol)
{
    const int r = blockIdx.x;
    const int g = r >> 9;
    const int n = r & 255;
    const int qrow = r & qmask;

    const int tid  = threadIdx.x;
    const int h    = tid >> 5;
    const int lane = tid & 31;

    __shared__ float qs[512];
    __shared__ float sim[8][16];

    qs[tid]       = Qr[(size_t)qrow * ldq + tid];
    qs[tid + 256] = Qr[(size_t)qrow * ldq + tid + 256];
    __syncthreads();

    float sc = -1e30f;
    float wl = 0.f;
    if (lane < Mu) {
        const float* kpl = msg_ptr(KVM, lane, g, n, &wl);
        const float4* k4 = reinterpret_cast<const float4*>(kpl + h * 64);
        const float4* q4 = reinterpret_cast<const float4*>(&qs[h * 64]);
        float s = 0.f;
#pragma unroll
        for (int t = 0; t < 16; t++) {
            float4 kk = k4[t];
            float4 qq = q4[t];
            s += qq.x * kk.x + qq.y * kk.y + qq.z * kk.z + qq.w * kk.w;
        }
        sc = s;
    }
    float mx = sc;
#pragma unroll
    for (int o = 16; o > 0; o >>= 1) mx = fmaxf(mx, __shfl_xor_sync(0xffffffffu, mx, o));
    float p = (lane < Mu) ? wl * __expf(sc - mx) : 0.f;
    if (lane < 16) sim[h][lane] = p;
    float ls = p;
#pragma unroll
    for (int o = 16; o > 0; o >>= 1) ls += __shfl_xor_sync(0xffffffffu, ls, o);
    __syncwarp();

    float o0 = 0.f, o1 = 0.f;
    for (int u = 0; u < Mu; u++) {
        float a = sim[h][u];
        float dummy;
        const float* vp = msg_ptr(KVM, u, g, n, &dummy) + 512;
        o0 += a * vp[h * 64 + lane];
        o1 += a * vp[h * 64 + lane + 32];
    }
    float inv = 1.0f / ls;
    __nv_bfloat16 hh, ll;
    split_bf16(o0 * inv, hh, ll);
    Oh[(size_t)r * 512 + h * 64 + lane] = hh;
    Ol[(size_t)r * 512 + h * 64 + lane] = ll;
    split_bf16(o1 * inv, hh, ll);
    Oh[(size_t)r * 512 + h * 64 + lane + 32] = hh;
    Ol[(size_t)r * 512 + h * 64 + lane + 32] = ll;
}

// ---------------- init: tokens -> compressed T (dup over g) ----------------
__global__ void init_tok(const float* __restrict__ tokens,
                         float* __restrict__ T,
                         __nv_bfloat16* __restrict__ Th, __nv_bfloat16* __restrict__ Tl)
{
    int idx = blockIdx.x * blockDim.x + threadIdx.x;
    if (idx >= CROWS * DIM) return;
    int d = idx & 511;
    int r = idx >> 9;
    int n = r & 255;
    int b = (r >> 8) & 1;
    float v = tokens[((size_t)(b * 256 + n)) * 512 + d];
    T[idx] = v;
    __nv_bfloat16 h, l;
    split_bf16(v, h, l);
    Th[idx] = h; Tl[idx] = l;
}

// ---------------- fused weight preparation ----------------
// Wbig FF rows interleaved: row 512+2e = sim_e, row 512+2e+1 = gate_e.
#define SEG0 1923072               // wbig: NBIG*512
#define SEG1 (SEG0 + 524288)       // wkv
#define SEG2 (SEG1 + 524288)       // rkv
#define SEG3 (SEG2 + 262144)       // rwo
#define SEG4 (SEG3 + 262144)       // woT
#define SEG5 (SEG4 + 720896)       // wvpT: [1408,512]
#define SEG6 (SEG5 + NBIG)         // bias
__global__ void prep_all(
    const float* __restrict__ wq, const float* __restrict__ ffk,
    const float* __restrict__ rq,
    const float* __restrict__ anw, const float* __restrict__ fnw,
    const float* __restrict__ rnw,
    const float* __restrict__ wkv, const float* __restrict__ rkv,
    const float* __restrict__ rwo, const float* __restrict__ wo,
    const float* __restrict__ wvals, const float* __restrict__ ffb,
    __nv_bfloat16* __restrict__ Wbigh, __nv_bfloat16* __restrict__ Wbigl,
    __nv_bfloat16* __restrict__ Wkvh,  __nv_bfloat16* __restrict__ Wkvl,
    __nv_bfloat16* __restrict__ Rkvh,  __nv_bfloat16* __restrict__ Rkvl,
    __nv_bfloat16* __restrict__ Rwoh,  __nv_bfloat16* __restrict__ Rwol,
    __nv_bfloat16* __restrict__ WoTh,  __nv_bfloat16* __restrict__ WoTl,
    __nv_bfloat16* __restrict__ WvpTh, __nv_bfloat16* __restrict__ WvpTl,
    float* __restrict__ bias)
{
    int idx = blockIdx.x * 256 + threadIdx.x;
    if (idx >= SEG6) return;
    __nv_bfloat16 h, l;
    if (idx < SEG0) {
        int row = idx >> 9, k = idx & 511;
        float v = 0.f;
        if (row < 512)            v = wq [(size_t)row * 512 + k] * anw[k];
        else if (row < QRES_OFF) {
            int i = row - 512;
            int e = i >> 1, odd = i & 1;
            int src = odd ? (DFF + e) : e;
            v = ffk[(size_t)src * 512 + k] * fnw[k];
        }
        else if (row < 3754)      v = rq [(size_t)(row - QRES_OFF) * 512 + k] * rnw[k];
        split_bf16(v, h, l);
        Wbigh[idx] = h; Wbigl[idx] = l;
    } else if (idx < SEG1) {
        int i = idx - SEG0;
        split_bf16(wkv[i], h, l);
        Wkvh[i] = h; Wkvl[i] = l;
    } else if (idx < SEG2) {
        int i = idx - SEG1;
        split_bf16(rkv[i], h, l);
        Rkvh[i] = h; Rkvl[i] = l;
    } else if (idx < SEG3) {
        int i = idx - SEG2;
        split_bf16(rwo[i], h, l);
        Rwoh[i] = h; Rwol[i] = l;
    } else if (idx < SEG4) {
        int i = idx - SEG3;
        int e = i >> 9, d = i & 511;
        split_bf16(wo[(size_t)d * 512 + e], h, l);
        WoTh[i] = h; WoTl[i] = l;
    } else if (idx < SEG5) {
        int i = idx - SEG4;
        int e = i >> 9, d = i & 511;      // WvpT[e,d] = wvals[d, e]
        float v = (e < DFF) ? wvals[(size_t)d * DFF + e] : 0.f;
        split_bf16(v, h, l);
        WvpTh[i] = h; WvpTl[i] = l;
    } else {
        int i = idx - SEG5;
        float v = 0.f;
        if (i >= 512 && i < QRES_OFF) {
            int j = i - 512;
            int e = j >> 1, odd = j & 1;
            v = ffb[odd ? (DFF + e) : e];
        }
        bias[i] = v;
    }
}

// bret[c] = sum_d ff_values_b[d] * res_wkv[c,d]; warp per c.
__global__ __launch_bounds__(256) void bret_fill(
    const float* __restrict__ rkv, const float* __restrict__ fvb,
    float* __restrict__ bret)
{
    int c    = blockIdx.x * 8 + (threadIdx.x >> 5);
    int lane = threadIdx.x & 31;
    const float* rp = rkv + (size_t)c * 512;
    float s = 0.f;
#pragma unroll
    for (int t = 0; t < 16; t++) s += rp[lane + t * 32] * fvb[lane + t * 32];
#pragma unroll
    for (int o = 16; o > 0; o >>= 1) s += __shfl_xor_sync(0xffffffffu, s, o);
    if (lane == 0) bret[c] = s;
}

// -------------------------------- launch --------------------------------------
static float* s_part = nullptr;

static inline GTask mk_task(const __nv_bfloat16* Ah, const __nv_bfloat16* Al, int lda,
                            const __nv_bfloat16* Bh, const __nv_bfloat16* Bl,
                            const float* bias, float* Yf,
                            __nv_bfloat16* Yh, __nv_bfloat16* Yl,
                            int M, int N, int K, int mode)
{
    GTask t;
    t.Ah = Ah; t.Al = Al; t.Bh = Bh; t.Bl = Bl; t.bias = bias;
    t.Yf = Yf; t.Yh = Yh; t.Yl = Yl;
    t.lda = lda; t.M = M; t.N = N; t.K = K; t.mode = mode;
    t.nx = (N + 63) / 64;
    t.nblocks = t.nx * (M / 128);
    return t;
}
static inline GTask empty_task() { GTask t = {}; t.nblocks = 0; t.nx = 1; return t; }

static inline void launch_group(GTask a, GTask b, GTask c)
{
    int total = a.nblocks + b.nblocks + c.nblocks;
    gemm_group<<<total, GTHREADS, GSMEM>>>(a, b, c);
}

extern "C" void kernel_launch(void* const* d_in, const int* in_sizes, int n_in,
                              void* d_out, int out_size)
{
    const float* tokens      = (const float*)d_in[0];
    const float* attn_norm_w = (const float*)d_in[1];
    const float* attn_wq     = (const float*)d_in[2];
    const float* attn_wkv    = (const float*)d_in[3];
    const float* attn_wo     = (const float*)d_in[4];
    const float* ff_norm_w   = (const float*)d_in[5];
    const float* ff_keys_w   = (const float*)d_in[6];
    const float* ff_keys_b   = (const float*)d_in[7];
    const float* ff_values_w = (const float*)d_in[8];
    const float* ff_values_b = (const float*)d_in[9];
    const float* res_norm_w  = (const float*)d_in[10];
    const float* res_wq      = (const float*)d_in[11];
    const float* res_wkv     = (const float*)d_in[12];
    const float* res_wo      = (const float*)d_in[13];
    float* out = (float*)d_out;

    cudaFuncSetAttribute(gemm_mma,   cudaFuncAttributeMaxDynamicSharedMemorySize, GSMEM);
    cudaFuncSetAttribute(gemm_group, cudaFuncAttributeMaxDynamicSharedMemorySize, GSMEM);

    float *B, *T, *KV, *kvm, *bias, *bret, *pacc, *pml;
    __nv_bfloat16 *XNh, *XNl, *XAh, *XAl, *ACTh, *ACTl, *XRh, *XRl, *Th, *Tl;
    __nv_bfloat16 *Wbigh, *Wbigl, *Wkvh, *Wkvl, *Rkvh, *Rkvl, *WoTh, *WoTl;
    __nv_bfloat16 *WvpTh, *WvpTl, *Rwoh, *Rwol, *Cath, *Catl, *Creth, *Cretl;
    cudaGetSymbolAddress((void**)&B,    g_B);
    cudaGetSymbolAddress((void**)&T,    g_T);
    cudaGetSymbolAddress((void**)&KV,   g_KV);
    cudaGetSymbolAddress((void**)&kvm,  g_kvm);
    cudaGetSymbolAddress((void**)&bias, g_bias);
    cudaGetSymbolAddress((void**)&bret, g_bret);
    cudaGetSymbolAddress((void**)&pacc, g_pacc);
    cudaGetSymbolAddress((void**)&pml,  g_pml);
    cudaGetSymbolAddress((void**)&s_part, g_part);
    cudaGetSymbolAddress((void**)&XNh,  g_XNh);  cudaGetSymbolAddress((void**)&XNl, g_XNl);
    cudaGetSymbolAddress((void**)&XAh,  g_XAh);  cudaGetSymbolAddress((void**)&XAl, g_XAl);
    cudaGetSymbolAddress((void**)&ACTh, g_ACTh); cudaGetSymbolAddress((void**)&ACTl, g_ACTl);
    cudaGetSymbolAddress((void**)&XRh,  g_XRh);  cudaGetSymbolAddress((void**)&XRl, g_XRl);
    cudaGetSymbolAddress((void**)&Th,   g_Th);   cudaGetSymbolAddress((void**)&Tl,  g_Tl);
    cudaGetSymbolAddress((void**)&Wbigh, g_Wbigh); cudaGetSymbolAddress((void**)&Wbigl, g_Wbigl);
    cudaGetSymbolAddress((void**)&Wkvh, g_Wkvh); cudaGetSymbolAddress((void**)&Wkvl, g_Wkvl);
    cudaGetSymbolAddress((void**)&Rkvh, g_Rkvh); cudaGetSymbolAddress((void**)&Rkvl, g_Rkvl);
    cudaGetSymbolAddress((void**)&WoTh, g_WoTh); cudaGetSymbolAddress((void**)&WoTl, g_WoTl);
    cudaGetSymbolAddress((void**)&WvpTh, g_WvpTh); cudaGetSymbolAddress((void**)&WvpTl, g_WvpTl);
    cudaGetSymbolAddress((void**)&Rwoh, g_Rwoh); cudaGetSymbolAddress((void**)&Rwol, g_Rwol);
    cudaGetSymbolAddress((void**)&Cath, g_Cath); cudaGetSymbolAddress((void**)&Catl, g_Catl);
    cudaGetSymbolAddress((void**)&Creth, g_Creth); cudaGetSymbolAddress((void**)&Cretl, g_Cretl);

    // prologue: weight prep + token init + bret
    init_tok<<<(CROWS * DIM + 255) / 256, 256>>>(tokens, T, Th, Tl);
    prep_all<<<(SEG6 + 255) / 256, 256>>>(
        attn_wq, ff_keys_w, res_wq, attn_norm_w, ff_norm_w, res_norm_w,
        attn_wkv, res_wkv, res_wo, attn_wo, ff_values_w, ff_keys_b,
        Wbigh, Wbigl, Wkvh, Wkvl, Rkvh, Rkvl, Rwoh, Rwol,
        WoTh, WoTl, WvpTh, WvpTl, bias);
    bret_fill<<<128, 256>>>(res_wkv, ff_values_b, bret);

    // grouped prologue GEMMs: C_att, Cret, tokens-kv
    launch_group(
        mk_task(Rkvh, Rkvl, 512, WoTh, WoTl, nullptr, nullptr, Cath, Catl,
                1024, 512, 512, 0),
        mk_task(Rkvh, Rkvl, 512, WvpTh, WvpTl, nullptr, nullptr, Creth, Cretl,
                1024, DFFP, 512, 0),
        mk_task(Th, Tl, 512, Rkvh, Rkvl, nullptr, kvm, nullptr, nullptr,
                512, 1024, 512, 0));

    for (int e = 0; e < 3; e++) {
        const int Mr = (e == 0) ? 512 : 1024;     // e0 is g-degenerate
        const int nb = Mr >> 8;
        float* kv_att = kvm + 524288 + (size_t)(e * 2 + 0) * 1048576;
        float* kv_ret = kvm + 524288 + (size_t)(e * 2 + 1) * 1048576;

        // e0: norm from init tokens; e1/e2: XN already produced by combine_rms
        if (e == 0)
            rmsnorm_now<<<Mr / 8, 256>>>(T, XNh, XNl, Mr);

        // GA: mega (fused geglu) + self-attn KV projection
        launch_group(
            mk_task(XNh, XNl, 512, Wbigh, Wbigl, bias, B, ACTh, ACTl,
                    Mr, NBIG, 512, 1),
            mk_task(Th, Tl, 512, Wkvh, Wkvl, nullptr, KV, nullptr, nullptr,
                    Mr, 1024, 512, 0),
            empty_task());

        self_attn_part<<<dim3(HEADS, nb, 4), 256>>>(B, NBIG, KV, pacc, pml, nb);
        self_attn_combine<<<nb * 8, 256>>>(pacc, pml, XAh, XAl, nb);

        // GB: attended kv (WO folded) + retrieved kv (FFV+RKV folded via Cret)
        launch_group(
            mk_task(XAh, XAl, 512, Cath, Catl, nullptr, kv_att, nullptr, nullptr,
                    Mr, 1024, 512, 0),
            mk_task(ACTh, ACTl, DFFP, Creth, Cretl, bret, kv_ret, nullptr, nullptr,
                    Mr, 1024, DFFP, 0),
            empty_task());

        // residual pooled attention over unique messages
        res_attn_kernel<<<CROWS, 256>>>(B + QRES_OFF, NBIG, (e == 0) ? 511 : 1023,
                                        kvm, 3 + 4 * e, XRh, XRl);

        // rwo GEMM via split-K (CROWS x 512 x 512, 32 base blocks -> s=4)
        {
            dim3 grid(8, CROWS / 128, 4);
            gemm_mma<<<grid, GTHREADS, GSMEM>>>(XRh, XRl, 512, Rwoh, Rwol, nullptr,
                                                nullptr, nullptr, nullptr,
                                                CROWS, 512, 512, 4, s_part, 0);
            if (e == 2) {
                int MN = CROWS * 512;
                splitk_combine<<<(MN / 2 + 255) / 256, 256>>>(
                    s_part, 4, MN, 512, nullptr, nullptr, nullptr, nullptr, out);
            } else {
                combine_rms<<<CROWS, 256>>>(s_part, 4, T, Th, Tl, XNh, XNl);
            }
        }
    }
}

// round 17
// speedup vs baseline: 1.1025x; 1.0571x over previous
#include <cuda_runtime.h>
#include <cuda_bf16.h>
#include <math.h>
#include <stdint.h>

#define DIM     512
#define HEADS   8
#define DFF     1365
#define DFFP    1408            // DFF padded (K multiple of 32)
#define CROWS   1024            // compressed rows: (g,b,n)
#define NBIG    3756            // 512 + 2730 + 512 + 2 align pad
#define QRES_OFF 3242           // 512 + 2730
#define RMS_EPS 1.1920929e-07f

// ---------------- scratch (device globals) ----------------
static __device__ float g_B   [CROWS * NBIG];     // [Q | (ff unused) | Qres]
static __device__ float g_T   [CROWS * DIM];
static __device__ float g_KV  [CROWS * 1024];
static __device__ float g_kvm [512 * 1024 + 6 * 1024 * 1024]; // tok + (att,ret)x3
static __device__ float g_bias[NBIG];
static __device__ float g_bret[1024];
static __device__ float g_pacc[128 * 64 * 256];
static __device__ float g_pml [128 * 2 * 256];
static __device__ float g_part[1 << 21];          // split-K partials

static __device__ __nv_bfloat16 g_XNh[CROWS * DIM],  g_XNl[CROWS * DIM];
static __device__ __nv_bfloat16 g_XAh[CROWS * DIM],  g_XAl[CROWS * DIM];
static __device__ __nv_bfloat16 g_ACTh[CROWS * DFFP], g_ACTl[CROWS * DFFP]; // pad cols stay 0
static __device__ __nv_bfloat16 g_XRh[CROWS * DIM],  g_XRl[CROWS * DIM];
static __device__ __nv_bfloat16 g_Th [CROWS * DIM],  g_Tl [CROWS * DIM];

static __device__ __nv_bfloat16 g_Wbigh[NBIG * 512], g_Wbigl[NBIG * 512];
static __device__ __nv_bfloat16 g_Wkvh[1024 * 512],  g_Wkvl[1024 * 512];
static __device__ __nv_bfloat16 g_Rkvh[1024 * 512],  g_Rkvl[1024 * 512];
static __device__ __nv_bfloat16 g_WoTh[512 * 512],   g_WoTl[512 * 512];
static __device__ __nv_bfloat16 g_WvpTh[DFFP * 512], g_WvpTl[DFFP * 512];
static __device__ __nv_bfloat16 g_Rwoh[512 * 512],   g_Rwol[512 * 512];
static __device__ __nv_bfloat16 g_Cath[1024 * 512],  g_Catl[1024 * 512];
static __device__ __nv_bfloat16 g_Creth[1024 * DFFP], g_Cretl[1024 * DFFP];

// ---------------- helpers ----------------
__device__ __forceinline__ void split_bf16(float v, __nv_bfloat16& h, __nv_bfloat16& l) {
    h = __float2bfloat16(v);
    l = __float2bfloat16(v - __bfloat162float(h));
}
__device__ __forceinline__ uint32_t smem_u32(const void* p) {
    uint32_t a;
    asm("{ .reg .u64 t; cvta.to.shared.u64 t, %1; cvt.u32.u64 %0, t; }" : "=r"(a) : "l"(p));
    return a;
}
__device__ __forceinline__ void cp16(uint32_t dst, const void* src, uint32_t sz) {
    asm volatile("cp.async.cg.shared.global [%0], [%1], 16, %2;"
                 :: "r"(dst), "l"(src), "r"(sz));
}
__device__ __forceinline__ void ldsm4(uint32_t& r0, uint32_t& r1, uint32_t& r2,
                                      uint32_t& r3, uint32_t addr) {
    asm volatile("ldmatrix.sync.aligned.m8n8.x4.shared.b16 {%0,%1,%2,%3}, [%4];"
                 : "=r"(r0), "=r"(r1), "=r"(r2), "=r"(r3) : "r"(addr));
}
__device__ __forceinline__ void mma16816(float* c, const uint32_t* a, const uint32_t* b) {
    asm volatile(
        "mma.sync.aligned.m16n8k16.row.col.f32.bf16.bf16.f32 "
        "{%0,%1,%2,%3}, {%4,%5,%6,%7}, {%8,%9}, {%0,%1,%2,%3};"
        : "+f"(c[0]), "+f"(c[1]), "+f"(c[2]), "+f"(c[3])
        : "r"(a[0]), "r"(a[1]), "r"(a[2]), "r"(a[3]), "r"(b[0]), "r"(b[1]));
}
__device__ __forceinline__ float gelu_pair(float sim, float gate) {
    return sim * (0.5f * gate * (1.0f + erff(gate * 0.70710678118654752440f)));
}

// ---------------- GEMM core (split-bf16, 3-stage cp.async; R11 config) ----------
// 128x64 block tile, 256 threads = 8 warps of 32x32 (4M x 2N layout).
#define GSTAGE   30720
#define GSMEM    (3 * GSTAGE)
#define GTHREADS 256

__device__ __forceinline__ void g_loads(
    uint32_t sb, int tid, int buf, int ck,
    const __nv_bfloat16* Ah, const __nv_bfloat16* Al, int lda,
    const __nv_bfloat16* Bh, const __nv_bfloat16* Bl,
    int K, int N, int bm0, int bn0)
{
    const uint32_t bufbase = sb + (uint32_t)buf * GSTAGE;
#pragma unroll
    for (int i = 0; i < 6; i++) {
        int c = tid + i * GTHREADS;
        int R = c >> 2;
        int q = c & 3;
        uint32_t dst = bufbase + (uint32_t)R * 80u + (uint32_t)q * 16u;
        const __nv_bfloat16* src;
        uint32_t sz = 16;
        if (R < 256) {
            src = (R < 128 ? Ah : Al) + (size_t)(bm0 + (R & 127)) * lda;
        } else {
            int rg = bn0 + (R & 63);
            if (rg >= N) { rg = 0; sz = 0; }
            src = (R < 320 ? Bh : Bl) + (size_t)rg * K;
        }
        cp16(dst, src + ck * 32 + q * 8, sz);
    }
    asm volatile("cp.async.commit_group;");
}

__device__ __forceinline__ void gemm_core(
    const __nv_bfloat16* Ah, const __nv_bfloat16* Al, int lda,
    const __nv_bfloat16* Bh, const __nv_bfloat16* Bl,
    const float* bias, float* Yf, __nv_bfloat16* Yh, __nv_bfloat16* Yl,
    int M, int N, int K, int splitk, float* Pf, int mode,
    int bn0, int bm0, int z)
{
    extern __shared__ __align__(16) char smem[];
    const uint32_t sb = smem_u32(smem);
    const int tid  = threadIdx.x;
    const int wid  = tid >> 5;
    const int lane = tid & 31;
    const int m0w  = (wid & 3) * 32;
    const int n0w  = (wid >> 2) * 32;

    float C[2][4][4];
#pragma unroll
    for (int mt = 0; mt < 2; mt++)
#pragma unroll
        for (int nt = 0; nt < 4; nt++)
#pragma unroll
            for (int v = 0; v < 4; v++) C[mt][nt][v] = 0.f;

    uint32_t aoffH[2], aoffL[2], boffH[2], boffL[2];
#pragma unroll
    for (int mt = 0; mt < 2; mt++) {
        uint32_t row = (uint32_t)(m0w + mt * 16 + (lane & 15));
        uint32_t kb  = (uint32_t)((lane >> 4) * 16);
        aoffH[mt] = sb + row * 80u + kb;
        aoffL[mt] = aoffH[mt] + 10240u;
    }
#pragma unroll
    for (int bt = 0; bt < 2; bt++) {
        uint32_t row = (uint32_t)(n0w + bt * 16 + (lane & 7) + ((lane >> 4) << 3));
        uint32_t kb  = (uint32_t)(((lane >> 3) & 1) * 16);
        boffH[bt] = sb + 20480u + row * 80u + kb;
        boffL[bt] = boffH[bt] + 5120u;
    }

    const int kspan = K / splitk;
    const int nk    = kspan >> 5;
    const int kb32  = z * nk;
    g_loads(sb, tid, 0, kb32 + 0, Ah, Al, lda, Bh, Bl, K, N, bm0, bn0);
    g_loads(sb, tid, 1, kb32 + 1, Ah, Al, lda, Bh, Bl, K, N, bm0, bn0);

    int buf = 0;
    for (int t = 0; t < nk; t++) {
        if (t < nk - 1) asm volatile("cp.async.wait_group 1;" ::: "memory");
        else            asm volatile("cp.async.wait_group 0;" ::: "memory");
        __syncthreads();

        if (t + 2 < nk) {
            int lb = buf + 2; if (lb >= 3) lb -= 3;
            g_loads(sb, tid, lb, kb32 + t + 2, Ah, Al, lda, Bh, Bl, K, N, bm0, bn0);
        }

        const uint32_t bofs = (uint32_t)buf * GSTAGE;
#pragma unroll
        for (int ks = 0; ks < 2; ks++) {
            const uint32_t ko = bofs + (uint32_t)ks * 32u;
            uint32_t ah[2][4], al[2][4], bh[4][2], bl[4][2];
#pragma unroll
            for (int mt = 0; mt < 2; mt++) {
                ldsm4(ah[mt][0], ah[mt][1], ah[mt][2], ah[mt][3], aoffH[mt] + ko);
                ldsm4(al[mt][0], al[mt][1], al[mt][2], al[mt][3], aoffL[mt] + ko);
            }
            ldsm4(bh[0][0], bh[0][1], bh[1][0], bh[1][1], boffH[0] + ko);
            ldsm4(bh[2][0], bh[2][1], bh[3][0], bh[3][1], boffH[1] + ko);
            ldsm4(bl[0][0], bl[0][1], bl[1][0], bl[1][1], boffL[0] + ko);
            ldsm4(bl[2][0], bl[2][1], bl[3][0], bl[3][1], boffL[1] + ko);
#pragma unroll
            for (int mt = 0; mt < 2; mt++)
#pragma unroll
                for (int nt = 0; nt < 4; nt++) {
                    mma16816(C[mt][nt], ah[mt], bh[nt]);
                    mma16816(C[mt][nt], ah[mt], bl[nt]);
                    mma16816(C[mt][nt], al[mt], bh[nt]);
                }
        }
        buf = (buf == 2) ? 0 : buf + 1;
    }

    if (splitk > 1) {
        float* P = Pf + (size_t)z * M * N;
#pragma unroll
        for (int mt = 0; mt < 2; mt++) {
            const int row = bm0 + m0w + mt * 16 + (lane >> 2);
#pragma unroll
            for (int nt = 0; nt < 4; nt++) {
                const int col = bn0 + n0w + nt * 8 + (lane & 3) * 2;
                if (col < N) {
                    *reinterpret_cast<float2*>(P + (size_t)row * N + col)
                        = make_float2(C[mt][nt][0], C[mt][nt][1]);
                    *reinterpret_cast<float2*>(P + (size_t)(row + 8) * N + col)
                        = make_float2(C[mt][nt][2], C[mt][nt][3]);
                }
            }
        }
        return;
    }

#pragma unroll
    for (int mt = 0; mt < 2; mt++) {
        const int row = bm0 + m0w + mt * 16 + (lane >> 2);
#pragma unroll
        for (int nt = 0; nt < 4; nt++) {
            const int col = bn0 + n0w + nt * 8 + (lane & 3) * 2;
            if (col < N) {
                float b0 = bias ? bias[col]     : 0.f;
                float b1 = bias ? bias[col + 1] : 0.f;
                float v00 = C[mt][nt][0] + b0, v01 = C[mt][nt][1] + b1;
                float v10 = C[mt][nt][2] + b0, v11 = C[mt][nt][3] + b1;
                if (mode == 1) {
                    if (col >= 512 && col < QRES_OFF) {
                        int e = (col - 512) >> 1;
                        float a0 = gelu_pair(v00, v01);
                        float a1 = gelu_pair(v10, v11);
                        __nv_bfloat16 h, l;
                        split_bf16(a0, h, l);
                        Yh[(size_t)row * DFFP + e] = h;
                        Yl[(size_t)row * DFFP + e] = l;
                        split_bf16(a1, h, l);
                        Yh[(size_t)(row + 8) * DFFP + e] = h;
                        Yl[(size_t)(row + 8) * DFFP + e] = l;
                    } else {
                        *reinterpret_cast<float2*>(Yf + (size_t)row * N + col)
                            = make_float2(v00, v01);
                        *reinterpret_cast<float2*>(Yf + (size_t)(row + 8) * N + col)
                            = make_float2(v10, v11);
                    }
                    continue;
                }
                const size_t o0 = (size_t)row * N + col;
                const size_t o1 = (size_t)(row + 8) * N + col;
                if (Yf) {
                    *reinterpret_cast<float2*>(Yf + o0) = make_float2(v00, v01);
                    *reinterpret_cast<float2*>(Yf + o1) = make_float2(v10, v11);
                }
                if (Yh) {
                    __nv_bfloat16 h0, l0, h1, l1;
                    split_bf16(v00, h0, l0); split_bf16(v01, h1, l1);
                    *reinterpret_cast<__nv_bfloat162*>(Yh + o0) = __nv_bfloat162(h0, h1);
                    *reinterpret_cast<__nv_bfloat162*>(Yl + o0) = __nv_bfloat162(l0, l1);
                    split_bf16(v10, h0, l0); split_bf16(v11, h1, l1);
                    *reinterpret_cast<__nv_bfloat162*>(Yh + o1) = __nv_bfloat162(h0, h1);
                    *reinterpret_cast<__nv_bfloat162*>(Yl + o1) = __nv_bfloat162(l0, l1);
                }
            }
        }
    }
}

// ---------------- single-task GEMM (supports split-K) ----------------
__global__ __launch_bounds__(GTHREADS) void gemm_mma(
    const __nv_bfloat16* __restrict__ Ah, const __nv_bfloat16* __restrict__ Al, int lda,
    const __nv_bfloat16* __restrict__ Bh, const __nv_bfloat16* __restrict__ Bl,
    const float* __restrict__ bias,
    float* __restrict__ Yf, __nv_bfloat16* __restrict__ Yh, __nv_bfloat16* __restrict__ Yl,
    int M, int N, int K, int splitk, float* __restrict__ Pf, int mode)
{
    gemm_core(Ah, Al, lda, Bh, Bl, bias, Yf, Yh, Yl, M, N, K, splitk, Pf, mode,
              blockIdx.x * 64, blockIdx.y * 128, blockIdx.z);
}

// ---------------- grouped GEMM (contiguous task ranges; R14 version) ------------
struct GTask {
    const __nv_bfloat16 *Ah, *Al, *Bh, *Bl;
    const float* bias;
    float* Yf;
    __nv_bfloat16 *Yh, *Yl;
    int lda, M, N, K, mode, nx, nblocks;
};

__global__ __launch_bounds__(GTHREADS) void gemm_group(GTask t0, GTask t1, GTask t2)
{
    int bx = blockIdx.x;
    GTask t;
    if (bx < t0.nblocks) { t = t0; }
    else if (bx < t0.nblocks + t1.nblocks) { t = t1; bx -= t0.nblocks; }
    else { t = t2; bx -= t0.nblocks + t1.nblocks; }
    int bn0 = (bx % t.nx) * 64;
    int bm0 = (bx / t.nx) * 128;
    gemm_core(t.Ah, t.Al, t.lda, t.Bh, t.Bl, t.bias, t.Yf, t.Yh, t.Yl,
              t.M, t.N, t.K, 1, nullptr, t.mode, bn0, bm0, 0);
}

// ---------------- split-K combine (optional expanded fanout output) -------------
__global__ __launch_bounds__(256) void splitk_combine(
    const float* __restrict__ P, int parts, int MN, int N,
    const float* __restrict__ bias,
    float* __restrict__ Yf,
    __nv_bfloat16* __restrict__ Yh, __nv_bfloat16* __restrict__ Yl,
    float* __restrict__ Yexp)
{
    int idx = (blockIdx.x * 256 + threadIdx.x) * 2;
    if (idx >= MN) return;
    float2 a = *reinterpret_cast<const float2*>(P + idx);
    for (int p = 1; p < parts; p++) {
        float2 b = *reinterpret_cast<const float2*>(P + (size_t)p * MN + idx);
        a.x += b.x; a.y += b.y;
    }
    if (bias) {
        int col = idx % N;
        a.x += bias[col];
        a.y += bias[col + 1];
    }
    if (Yexp) {
        int row = idx / N;
        int col = idx - row * N;
        int g   = row >> 9;
        int rem = row & 511;
#pragma unroll
        for (int j = 0; j < 3; j++) {
            int r2 = ((3 * g + j) << 9) + rem;
            *reinterpret_cast<float2*>(Yexp + (size_t)r2 * N + col) = a;
        }
        return;
    }
    if (Yf) *reinterpret_cast<float2*>(Yf + idx) = a;
    if (Yh) {
        __nv_bfloat16 h0, l0, h1, l1;
        split_bf16(a.x, h0, l0); split_bf16(a.y, h1, l1);
        *reinterpret_cast<__nv_bfloat162*>(Yh + idx) = __nv_bfloat162(h0, h1);
        *reinterpret_cast<__nv_bfloat162*>(Yl + idx) = __nv_bfloat162(l0, l1);
    }
}

// ---------------- fused split-K combine + RMSNorm (block per 512-col row) -------
__global__ __launch_bounds__(256) void combine_rms(
    const float* __restrict__ P, int parts,
    float* __restrict__ T,
    __nv_bfloat16* __restrict__ Th, __nv_bfloat16* __restrict__ Tl,
    __nv_bfloat16* __restrict__ XNh, __nv_bfloat16* __restrict__ XNl)
{
    const int row = blockIdx.x;
    const int tid = threadIdx.x;
    const int idx = row * DIM + tid * 2;
    const int MN  = CROWS * DIM;

    __shared__ float red[8];

    float2 a = *reinterpret_cast<const float2*>(P + idx);
    for (int p = 1; p < parts; p++) {
        float2 b = *reinterpret_cast<const float2*>(P + (size_t)p * MN + idx);
        a.x += b.x; a.y += b.y;
    }

    *reinterpret_cast<float2*>(T + idx) = a;
    __nv_bfloat16 h0, l0, h1, l1;
    split_bf16(a.x, h0, l0); split_bf16(a.y, h1, l1);
    *reinterpret_cast<__nv_bfloat162*>(Th + idx) = __nv_bfloat162(h0, h1);
    *reinterpret_cast<__nv_bfloat162*>(Tl + idx) = __nv_bfloat162(l0, l1);

    float ss = a.x * a.x + a.y * a.y;
#pragma unroll
    for (int o = 16; o > 0; o >>= 1) ss += __shfl_xor_sync(0xffffffffu, ss, o);
    if ((tid & 31) == 0) red[tid >> 5] = ss;
    __syncthreads();
    if (tid < 8) {
        float v = red[tid];
#pragma unroll
        for (int o = 4; o > 0; o >>= 1) v += __shfl_xor_sync(0xffu, v, o);
        if (tid == 0) red[0] = v;
    }
    __syncthreads();
    float rs = rsqrtf(red[0] * (1.0f / 512.0f) + RMS_EPS);

    split_bf16(a.x * rs, h0, l0); split_bf16(a.y * rs, h1, l1);
    *reinterpret_cast<__nv_bfloat162*>(XNh + idx) = __nv_bfloat162(h0, h1);
    *reinterpret_cast<__nv_bfloat162*>(XNl + idx) = __nv_bfloat162(l0, l1);
}

// ---------------- packed f32x2 helpers ----------------
__device__ __forceinline__ void ffma2(unsigned long long& d, unsigned long long a,
                                      unsigned long long b) {
    asm("fma.rn.f32x2 %0, %1, %2, %0;" : "+l"(d) : "l"(a), "l"(b));
}
__device__ __forceinline__ unsigned long long fma2_3(unsigned long long a,
                                                     unsigned long long b,
                                                     unsigned long long c) {
    unsigned long long d;
    asm("fma.rn.f32x2 %0, %1, %2, %3;" : "=l"(d) : "l"(a), "l"(b), "l"(c));
    return d;
}
__device__ __forceinline__ unsigned long long mul2(unsigned long long a,
                                                   unsigned long long b) {
    unsigned long long d;
    asm("mul.rn.f32x2 %0, %1, %2;" : "=l"(d) : "l"(a), "l"(b));
    return d;
}
__device__ __forceinline__ unsigned long long dup2(float x) {
    unsigned long long r;
    asm("mov.b64 %0, {%1, %1};" : "=l"(r) : "f"(x));
    return r;
}
__device__ __forceinline__ unsigned long long pk2(float x, float y) {
    unsigned long long r;
    asm("mov.b64 %0, {%1, %2};" : "=l"(r) : "f"(x), "f"(y));
    return r;
}
__device__ __forceinline__ float2 unpack2(unsigned long long v) {
    float2 f;
    asm("mov.b64 {%0, %1}, %2;" : "=f"(f.x), "=f"(f.y) : "l"(v));
    return f;
}

// ---------------- RMSNorm (used only for exchange 0 on init tokens) -------------
__global__ __launch_bounds__(256) void rmsnorm_now(
    const float* __restrict__ X,
    __nv_bfloat16* __restrict__ Yh, __nv_bfloat16* __restrict__ Yl, int rows)
{
    int row  = blockIdx.x * 8 + (threadIdx.x >> 5);
    int lane = threadIdx.x & 31;
    if (row >= rows) return;
    const float* xp = X + (size_t)row * DIM;
    float x[16];
    float ss = 0.f;
#pragma unroll
    for (int t = 0; t < 16; t++) { x[t] = xp[lane + t * 32]; ss += x[t] * x[t]; }
#pragma unroll
    for (int o = 16; o > 0; o >>= 1) ss += __shfl_xor_sync(0xffffffffu, ss, o);
    float rs = rsqrtf(ss * (1.0f / 512.0f) + RMS_EPS);
#pragma unroll
    for (int t = 0; t < 16; t++) {
        int c = lane + t * 32;
        __nv_bfloat16 h, l;
        split_bf16(x[t] * rs, h, l);
        Yh[(size_t)row * DIM + c] = h;
        Yl[(size_t)row * DIM + c] = l;
    }
}

// ---------------- Self attention, split over 4 key-chunks ----------------
__global__ __launch_bounds__(256) void self_attn_part(
    const float* __restrict__ Q, int ldq, const float* __restrict__ KV,
    float* __restrict__ pacc, float* __restrict__ pml, int nbatch)
{
    const int h     = blockIdx.x;
    const int batch = blockIdx.y;
    const int jc    = blockIdx.z;
    const int i     = threadIdx.x;
    const int j0    = jc * 64;

    __shared__ __align__(16) float Ks[64][64];
    __shared__ __align__(16) float Vs[64][64];

    unsigned long long qp[32];
    {
        const float4* qq = reinterpret_cast<const float4*>(
            Q + ((size_t)(batch * 256 + i)) * ldq + h * 64);
#pragma unroll
        for (int t = 0; t < 16; t++) {
            float4 v = qq[t];
            qp[2 * t]     = pk2(v.x, v.y);
            qp[2 * t + 1] = pk2(v.z, v.w);
        }
    }

#pragma unroll
    for (int s = 0; s < 4; s++) {
        int u  = threadIdx.x + s * 256;
        int jr = u >> 4;
        int c4 = u & 15;
        const float* kp = KV + ((size_t)(batch * 256 + j0 + jr)) * 1024 + h * 64 + c4 * 4;
        *reinterpret_cast<float4*>(&Ks[jr][c4 * 4]) = *reinterpret_cast<const float4*>(kp);
        *reinterpret_cast<float4*>(&Vs[jr][c4 * 4]) = *reinterpret_cast<const float4*>(kp + 512);
    }
    __syncthreads();

    float m = -1e30f, l = 0.f;
    unsigned long long acc[32];
#pragma unroll
    for (int t = 0; t < 32; t++) acc[t] = 0ull;

    for (int j = 0; j < 64; j++) {
        const ulonglong2* kr = reinterpret_cast<const ulonglong2*>(Ks[j]);
        unsigned long long s0 = 0ull, s1 = 0ull;
#pragma unroll
        for (int t = 0; t < 8; t++) {
            ulonglong2 k0 = kr[2 * t];
            ulonglong2 k1 = kr[2 * t + 1];
            ffma2(s0, qp[4 * t + 0], k0.x);
            ffma2(s1, qp[4 * t + 1], k0.y);
            ffma2(s0, qp[4 * t + 2], k1.x);
            ffma2(s1, qp[4 * t + 3], k1.y);
        }
        float2 sa = unpack2(s0), sb = unpack2(s1);
        float s = (sa.x + sa.y) + (sb.x + sb.y);

        float mn = fmaxf(m, s);
        float f  = __expf(m - mn);
        float p  = __expf(s - mn);
        l = l * f + p;
        unsigned long long fd = dup2(f), pd = dup2(p);
        const ulonglong2* vr = reinterpret_cast<const ulonglong2*>(Vs[j]);
#pragma unroll
        for (int t = 0; t < 16; t++) {
            ulonglong2 vv = vr[t];
            acc[2 * t]     = fma2_3(acc[2 * t],     fd, mul2(vv.x, pd));
            acc[2 * t + 1] = fma2_3(acc[2 * t + 1], fd, mul2(vv.y, pd));
        }
        m = mn;
    }

    const int bl = (jc * nbatch + batch) * HEADS + h;
    float* pa = pacc + ((size_t)bl * 64) * 256;
#pragma unroll
    for (int t = 0; t < 32; t++) {
        float2 a = unpack2(acc[t]);
        pa[(2 * t) * 256 + i]     = a.x;
        pa[(2 * t + 1) * 256 + i] = a.y;
    }
    pml[(bl * 2 + 0) * 256 + i] = m;
    pml[(bl * 2 + 1) * 256 + i] = l;
}

__global__ __launch_bounds__(256) void self_attn_combine(
    const float* __restrict__ pacc, const float* __restrict__ pml,
    __nv_bfloat16* __restrict__ Oh, __nv_bfloat16* __restrict__ Ol, int nbatch)
{
    int idx   = blockIdx.x * 256 + threadIdx.x;
    int i     = idx & 255;
    int h     = (idx >> 8) & 7;
    int batch = idx >> 11;

    float mc[4], lc[4];
    float M = -1e30f;
#pragma unroll
    for (int c = 0; c < 4; c++) {
        int bl = (c * nbatch + batch) * HEADS + h;
        mc[c] = pml[(bl * 2 + 0) * 256 + i];
        lc[c] = pml[(bl * 2 + 1) * 256 + i];
        M = fmaxf(M, mc[c]);
    }
    float w[4];
    float L = 0.f;
#pragma unroll
    for (int c = 0; c < 4; c++) { w[c] = __expf(mc[c] - M); L += lc[c] * w[c]; }
    float inv = 1.0f / L;

    size_t ob = ((size_t)(batch * 256 + i)) * 512 + h * 64;
#pragma unroll
    for (int t = 0; t < 64; t++) {
        float o = 0.f;
#pragma unroll
        for (int c = 0; c < 4; c++) {
            int bl = (c * nbatch + batch) * HEADS + h;
            o += w[c] * pacc[((size_t)bl * 64 + t) * 256 + i];
        }
        __nv_bfloat16 hh, ll;
        split_bf16(o * inv, hh, ll);
        Oh[ob + t] = hh;
        Ol[ob + t] = ll;
    }
}

// ---------------- Residual attention over unique messages ----------------
__device__ __forceinline__ const float* msg_ptr(
    const float* KVM, int u, int g, int n, float* w)
{
    if (u == 0) { *w = 6.f; return KVM + ((size_t)(g * 256 + n)) * 1024; }
    if (u <= 2) { *w = 6.f;
        return KVM + 524288u + (size_t)(u - 1) * 1048576u + ((size_t)(g * 256 + n)) * 1024; }
    int j = 1 + ((u - 3) >> 2), t = (u - 3) & 3;
    int type = t >> 1, gpp = t & 1;
    *w = 3.f;
    return KVM + 524288u + ((size_t)(j * 2 + type)) * 1048576u
         + ((size_t)((gpp * 2 + g) * 256 + n)) * 1024;
}

__global__ __launch_bounds__(256) void res_attn_kernel(
    const float* __restrict__ Qr, int ldq, int qmask,
    const float* __restrict__ KVM, int Mu,
    __nv_bfloat16* __restrict__ Oh, __nv_bfloat16* __restrict__ Ol)
{
    const int r = blockIdx.x;
    const int g = r >> 9;
    const int n = r & 255;
    const int qrow = r & qmask;

    const int tid  = threadIdx.x;
    const int h    = tid >> 5;
    const int lane = tid & 31;

    __shared__ float qs[512];
    __shared__ float sim[8][16];

    qs[tid]       = Qr[(size_t)qrow * ldq + tid];
    qs[tid + 256] = Qr[(size_t)qrow * ldq + tid + 256];
    __syncthreads();

    float sc = -1e30f;
    float wl = 0.f;
    if (lane < Mu) {
        const float* kpl = msg_ptr(KVM, lane, g, n, &wl);
        const float4* k4 = reinterpret_cast<const float4*>(kpl + h * 64);
        const float4* q4 = reinterpret_cast<const float4*>(&qs[h * 64]);
        float s = 0.f;
#pragma unroll
        for (int t = 0; t < 16; t++) {
            float4 kk = k4[t];
            float4 qq = q4[t];
            s += qq.x * kk.x + qq.y * kk.y + qq.z * kk.z + qq.w * kk.w;
        }
        sc = s;
    }
    float mx = sc;
#pragma unroll
    for (int o = 16; o > 0; o >>= 1) mx = fmaxf(mx, __shfl_xor_sync(0xffffffffu, mx, o));
    float p = (lane < Mu) ? wl * __expf(sc - mx) : 0.f;
    if (lane < 16) sim[h][lane] = p;
    float ls = p;
#pragma unroll
    for (int o = 16; o > 0; o >>= 1) ls += __shfl_xor_sync(0xffffffffu, ls, o);
    __syncwarp();

    float o0 = 0.f, o1 = 0.f;
    for (int u = 0; u < Mu; u++) {
        float a = sim[h][u];
        float dummy;
        const float* vp = msg_ptr(KVM, u, g, n, &dummy) + 512;
        o0 += a * vp[h * 64 + lane];
        o1 += a * vp[h * 64 + lane + 32];
    }
    float inv = 1.0f / ls;
    __nv_bfloat16 hh, ll;
    split_bf16(o0 * inv, hh, ll);
    Oh[(size_t)r * 512 + h * 64 + lane] = hh;
    Ol[(size_t)r * 512 + h * 64 + lane] = ll;
    split_bf16(o1 * inv, hh, ll);
    Oh[(size_t)r * 512 + h * 64 + lane + 32] = hh;
    Ol[(size_t)r * 512 + h * 64 + lane + 32] = ll;
}

// ---------------- init: tokens -> compressed T (dup over g) ----------------
__global__ void init_tok(const float* __restrict__ tokens,
                         float* __restrict__ T,
                         __nv_bfloat16* __restrict__ Th, __nv_bfloat16* __restrict__ Tl)
{
    int idx = blockIdx.x * blockDim.x + threadIdx.x;
    if (idx >= CROWS * DIM) return;
    int d = idx & 511;
    int r = idx >> 9;
    int n = r & 255;
    int b = (r >> 8) & 1;
    float v = tokens[((size_t)(b * 256 + n)) * 512 + d];
    T[idx] = v;
    __nv_bfloat16 h, l;
    split_bf16(v, h, l);
    Th[idx] = h; Tl[idx] = l;
}

// ---------------- fused weight preparation ----------------
// Wbig FF rows interleaved: row 512+2e = sim_e, row 512+2e+1 = gate_e.
#define SEG0 1923072               // wbig: NBIG*512
#define SEG1 (SEG0 + 524288)       // wkv
#define SEG2 (SEG1 + 524288)       // rkv
#define SEG3 (SEG2 + 262144)       // rwo
#define SEG4 (SEG3 + 262144)       // woT
#define SEG5 (SEG4 + 720896)       // wvpT: [1408,512]
#define SEG6 (SEG5 + NBIG)         // bias
__global__ void prep_all(
    const float* __restrict__ wq, const float* __restrict__ ffk,
    const float* __restrict__ rq,
    const float* __restrict__ anw, const float* __restrict__ fnw,
    const float* __restrict__ rnw,
    const float* __restrict__ wkv, const float* __restrict__ rkv,
    const float* __restrict__ rwo, const float* __restrict__ wo,
    const float* __restrict__ wvals, const float* __restrict__ ffb,
    __nv_bfloat16* __restrict__ Wbigh, __nv_bfloat16* __restrict__ Wbigl,
    __nv_bfloat16* __restrict__ Wkvh,  __nv_bfloat16* __restrict__ Wkvl,
    __nv_bfloat16* __restrict__ Rkvh,  __nv_bfloat16* __restrict__ Rkvl,
    __nv_bfloat16* __restrict__ Rwoh,  __nv_bfloat16* __restrict__ Rwol,
    __nv_bfloat16* __restrict__ WoTh,  __nv_bfloat16* __restrict__ WoTl,
    __nv_bfloat16* __restrict__ WvpTh, __nv_bfloat16* __restrict__ WvpTl,
    float* __restrict__ bias)
{
    int idx = blockIdx.x * 256 + threadIdx.x;
    if (idx >= SEG6) return;
    __nv_bfloat16 h, l;
    if (idx < SEG0) {
        int row = idx >> 9, k = idx & 511;
        float v = 0.f;
        if (row < 512)            v = wq [(size_t)row * 512 + k] * anw[k];
        else if (row < QRES_OFF) {
            int i = row - 512;
            int e = i >> 1, odd = i & 1;
            int src = odd ? (DFF + e) : e;
            v = ffk[(size_t)src * 512 + k] * fnw[k];
        }
        else if (row < 3754)      v = rq [(size_t)(row - QRES_OFF) * 512 + k] * rnw[k];
        split_bf16(v, h, l);
        Wbigh[idx] = h; Wbigl[idx] = l;
    } else if (idx < SEG1) {
        int i = idx - SEG0;
        split_bf16(wkv[i], h, l);
        Wkvh[i] = h; Wkvl[i] = l;
    } else if (idx < SEG2) {
        int i = idx - SEG1;
        split_bf16(rkv[i], h, l);
        Rkvh[i] = h; Rkvl[i] = l;
    } else if (idx < SEG3) {
        int i = idx - SEG2;
        split_bf16(rwo[i], h, l);
        Rwoh[i] = h; Rwol[i] = l;
    } else if (idx < SEG4) {
        int i = idx - SEG3;
        int e = i >> 9, d = i & 511;
        split_bf16(wo[(size_t)d * 512 + e], h, l);
        WoTh[i] = h; WoTl[i] = l;
    } else if (idx < SEG5) {
        int i = idx - SEG4;
        int e = i >> 9, d = i & 511;      // WvpT[e,d] = wvals[d, e]
        float v = (e < DFF) ? wvals[(size_t)d * DFF + e] : 0.f;
        split_bf16(v, h, l);
        WvpTh[i] = h; WvpTl[i] = l;
    } else {
        int i = idx - SEG5;
        float v = 0.f;
        if (i >= 512 && i < QRES_OFF) {
            int j = i - 512;
            int e = j >> 1, odd = j & 1;
            v = ffb[odd ? (DFF + e) : e];
        }
        bias[i] = v;
    }
}

// bret[c] = sum_d ff_values_b[d] * res_wkv[c,d]; warp per c.
__global__ __launch_bounds__(256) void bret_fill(
    const float* __restrict__ rkv, const float* __restrict__ fvb,
    float* __restrict__ bret)
{
    int c    = blockIdx.x * 8 + (threadIdx.x >> 5);
    int lane = threadIdx.x & 31;
    const float* rp = rkv + (size_t)c * 512;
    float s = 0.f;
#pragma unroll
    for (int t = 0; t < 16; t++) s += rp[lane + t * 32] * fvb[lane + t * 32];
#pragma unroll
    for (int o = 16; o > 0; o >>= 1) s += __shfl_xor_sync(0xffffffffu, s, o);
    if (lane == 0) bret[c] = s;
}

// -------------------------------- launch --------------------------------------
static float* s_part = nullptr;
static cudaStream_t s_str1 = nullptr;
static cudaEvent_t  s_evF  = nullptr;
static cudaEvent_t  s_evJ  = nullptr;

static inline GTask mk_task(const __nv_bfloat16* Ah, const __nv_bfloat16* Al, int lda,
                            const __nv_bfloat16* Bh, const __nv_bfloat16* Bl,
                            const float* bias, float* Yf,
                            __nv_bfloat16* Yh, __nv_bfloat16* Yl,
                            int M, int N, int K, int mode)
{
    GTask t;
    t.Ah = Ah; t.Al = Al; t.Bh = Bh; t.Bl = Bl; t.bias = bias;
    t.Yf = Yf; t.Yh = Yh; t.Yl = Yl;
    t.lda = lda; t.M = M; t.N = N; t.K = K; t.mode = mode;
    t.nx = (N + 63) / 64;
    t.nblocks = t.nx * (M / 128);
    return t;
}
static inline GTask empty_task() { GTask t = {}; t.nblocks = 0; t.nx = 1; return t; }

static inline void launch_group(GTask a, GTask b, GTask c)
{
    int total = a.nblocks + b.nblocks + c.nblocks;
    gemm_group<<<total, GTHREADS, GSMEM>>>(a, b, c);
}

extern "C" void kernel_launch(void* const* d_in, const int* in_sizes, int n_in,
                              void* d_out, int out_size)
{
    const float* tokens      = (const float*)d_in[0];
    const float* attn_norm_w = (const float*)d_in[1];
    const float* attn_wq     = (const float*)d_in[2];
    const float* attn_wkv    = (const float*)d_in[3];
    const float* attn_wo     = (const float*)d_in[4];
    const float* ff_norm_w   = (const float*)d_in[5];
    const float* ff_keys_w   = (const float*)d_in[6];
    const float* ff_keys_b   = (const float*)d_in[7];
    const float* ff_values_w = (const float*)d_in[8];
    const float* ff_values_b = (const float*)d_in[9];
    const float* res_norm_w  = (const float*)d_in[10];
    const float* res_wq      = (const float*)d_in[11];
    const float* res_wkv     = (const float*)d_in[12];
    const float* res_wo      = (const float*)d_in[13];
    float* out = (float*)d_out;

    cudaFuncSetAttribute(gemm_mma,   cudaFuncAttributeMaxDynamicSharedMemorySize, GSMEM);
    cudaFuncSetAttribute(gemm_group, cudaFuncAttributeMaxDynamicSharedMemorySize, GSMEM);

    if (!s_str1) {
        cudaStreamCreateWithFlags(&s_str1, cudaStreamNonBlocking);
        cudaEventCreateWithFlags(&s_evF, cudaEventDisableTiming);
        cudaEventCreateWithFlags(&s_evJ, cudaEventDisableTiming);
    }

    float *B, *T, *KV, *kvm, *bias, *bret, *pacc, *pml;
    __nv_bfloat16 *XNh, *XNl, *XAh, *XAl, *ACTh, *ACTl, *XRh, *XRl, *Th, *Tl;
    __nv_bfloat16 *Wbigh, *Wbigl, *Wkvh, *Wkvl, *Rkvh, *Rkvl, *WoTh, *WoTl;
    __nv_bfloat16 *WvpTh, *WvpTl, *Rwoh, *Rwol, *Cath, *Catl, *Creth, *Cretl;
    cudaGetSymbolAddress((void**)&B,    g_B);
    cudaGetSymbolAddress((void**)&T,    g_T);
    cudaGetSymbolAddress((void**)&KV,   g_KV);
    cudaGetSymbolAddress((void**)&kvm,  g_kvm);
    cudaGetSymbolAddress((void**)&bias, g_bias);
    cudaGetSymbolAddress((void**)&bret, g_bret);
    cudaGetSymbolAddress((void**)&pacc, g_pacc);
    cudaGetSymbolAddress((void**)&pml,  g_pml);
    cudaGetSymbolAddress((void**)&s_part, g_part);
    cudaGetSymbolAddress((void**)&XNh,  g_XNh);  cudaGetSymbolAddress((void**)&XNl, g_XNl);
    cudaGetSymbolAddress((void**)&XAh,  g_XAh);  cudaGetSymbolAddress((void**)&XAl, g_XAl);
    cudaGetSymbolAddress((void**)&ACTh, g_ACTh); cudaGetSymbolAddress((void**)&ACTl, g_ACTl);
    cudaGetSymbolAddress((void**)&XRh,  g_XRh);  cudaGetSymbolAddress((void**)&XRl, g_XRl);
    cudaGetSymbolAddress((void**)&Th,   g_Th);   cudaGetSymbolAddress((void**)&Tl,  g_Tl);
    cudaGetSymbolAddress((void**)&Wbigh, g_Wbigh); cudaGetSymbolAddress((void**)&Wbigl, g_Wbigl);
    cudaGetSymbolAddress((void**)&Wkvh, g_Wkvh); cudaGetSymbolAddress((void**)&Wkvl, g_Wkvl);
    cudaGetSymbolAddress((void**)&Rkvh, g_Rkvh); cudaGetSymbolAddress((void**)&Rkvl, g_Rkvl);
    cudaGetSymbolAddress((void**)&WoTh, g_WoTh); cudaGetSymbolAddress((void**)&WoTl, g_WoTl);
    cudaGetSymbolAddress((void**)&WvpTh, g_WvpTh); cudaGetSymbolAddress((void**)&WvpTl, g_WvpTl);
    cudaGetSymbolAddress((void**)&Rwoh, g_Rwoh); cudaGetSymbolAddress((void**)&Rwol, g_Rwol);
    cudaGetSymbolAddress((void**)&Cath, g_Cath); cudaGetSymbolAddress((void**)&Catl, g_Catl);
    cudaGetSymbolAddress((void**)&Creth, g_Creth); cudaGetSymbolAddress((void**)&Cretl, g_Cretl);

    // prologue: weight prep + token init + bret
    init_tok<<<(CROWS * DIM + 255) / 256, 256>>>(tokens, T, Th, Tl);
    prep_all<<<(SEG6 + 255) / 256, 256>>>(
        attn_wq, ff_keys_w, res_wq, attn_norm_w, ff_norm_w, res_norm_w,
        attn_wkv, res_wkv, res_wo, attn_wo, ff_values_w, ff_keys_b,
        Wbigh, Wbigl, Wkvh, Wkvl, Rkvh, Rkvl, Rwoh, Rwol,
        WoTh, WoTl, WvpTh, WvpTl, bias);
    bret_fill<<<128, 256>>>(res_wkv, ff_values_b, bret);

    // grouped prologue GEMMs: C_att, Cret, tokens-kv
    launch_group(
        mk_task(Rkvh, Rkvl, 512, WoTh, WoTl, nullptr, nullptr, Cath, Catl,
                1024, 512, 512, 0),
        mk_task(Rkvh, Rkvl, 512, WvpTh, WvpTl, nullptr, nullptr, Creth, Cretl,
                1024, DFFP, 512, 0),
        mk_task(Th, Tl, 512, Rkvh, Rkvl, nullptr, kvm, nullptr, nullptr,
                512, 1024, 512, 0));

    for (int e = 0; e < 3; e++) {
        const int Mr = (e == 0) ? 512 : 1024;     // e0 is g-degenerate
        const int nb = Mr >> 8;
        float* kv_att = kvm + 524288 + (size_t)(e * 2 + 0) * 1048576;
        float* kv_ret = kvm + 524288 + (size_t)(e * 2 + 1) * 1048576;

        // e0: norm from init tokens; e1/e2: XN already produced by combine_rms
        if (e == 0)
            rmsnorm_now<<<Mr / 8, 256>>>(T, XNh, XNl, Mr);

        // GA: mega (fused geglu) + self-attn KV projection
        launch_group(
            mk_task(XNh, XNl, 512, Wbigh, Wbigl, bias, B, ACTh, ACTl,
                    Mr, NBIG, 512, 1),
            mk_task(Th, Tl, 512, Wkvh, Wkvl, nullptr, KV, nullptr, nullptr,
                    Mr, 1024, 512, 0),
            empty_task());

        // fork: kv_ret depends only on ACT (GA) -> run on side stream,
        // overlapping the attention chain on the main stream.
        cudaEventRecord(s_evF, 0);
        cudaStreamWaitEvent(s_str1, s_evF, 0);
        {
            dim3 grid(16, Mr / 128);
            gemm_mma<<<grid, GTHREADS, GSMEM, s_str1>>>(
                ACTh, ACTl, DFFP, Creth, Cretl, bret,
                kv_ret, nullptr, nullptr, Mr, 1024, DFFP, 1, nullptr, 0);
        }
        cudaEventRecord(s_evJ, s_str1);

        // main stream: attention chain + kv_att
        self_attn_part<<<dim3(HEADS, nb, 4), 256>>>(B, NBIG, KV, pacc, pml, nb);
        self_attn_combine<<<nb * 8, 256>>>(pacc, pml, XAh, XAl, nb);
        {
            dim3 grid(16, Mr / 128);
            gemm_mma<<<grid, GTHREADS, GSMEM>>>(
                XAh, XAl, 512, Cath, Catl, nullptr,
                kv_att, nullptr, nullptr, Mr, 1024, 512, 1, nullptr, 0);
        }
        cudaStreamWaitEvent(0, s_evJ, 0);

        // residual pooled attention over unique messages
        res_attn_kernel<<<CROWS, 256>>>(B + QRES_OFF, NBIG, (e == 0) ? 511 : 1023,
                                        kvm, 3 + 4 * e, XRh, XRl);

        // rwo GEMM via split-K (CROWS x 512 x 512, 32 base blocks -> s=4)
        {
            dim3 grid(8, CROWS / 128, 4);
            gemm_mma<<<grid, GTHREADS, GSMEM>>>(XRh, XRl, 512, Rwoh, Rwol, nullptr,
                                                nullptr, nullptr, nullptr,
                                                CROWS, 512, 512, 4, s_part, 0);
            if (e == 2) {
                int MN = CROWS * 512;
                splitk_combine<<<(MN / 2 + 255) / 256, 256>>>(
                    s_part, 4, MN, 512, nullptr, nullptr, nullptr, nullptr, out);
            } else {
                combine_rms<<<CROWS, 256>>>(s_part, 4, T, Th, Tl, XNh, XNl);
            }
        }
    }
}